// round 4
// baseline (speedup 1.0000x reference)
#include <cuda_runtime.h>
#include <math.h>

#define C_NB 2
#define C_NL 48
#define C_NN 3000
#define C_ND 128
#define C_NLOUT 24
#define C_BN (C_NB*C_NN)
#define C_ROWS (C_BN*C_NL)
#define C_BL (C_NB*C_NL)

// ---------------- device-global scratch ----------------
__device__ float g_mean[C_BN];
__device__ float g_enc [C_ROWS*C_ND];
__device__ float g_h   [C_ROWS*C_ND];
__device__ float g_q   [C_ROWS*C_ND];
__device__ float g_kk  [C_ROWS*C_ND];
__device__ float g_v   [C_ROWS*C_ND];
__device__ float g_att0[C_ROWS*C_ND];
__device__ float g_ff  [C_ROWS*512];
__device__ float g_nf  [C_NN*C_BL*C_ND];
__device__ float g_agg [C_NN*C_BL*C_ND];
__device__ float g_pe  [C_NN*C_ND];
__device__ float g_pe2 [C_NN*C_ND];
__device__ float g_pw  [(size_t)C_NN*C_ND*C_ND];
__device__ float g_res [C_NN*C_BL*C_ND];
__device__ float g_gmu [C_BL*4];
__device__ float g_grs [C_BL*4];

__device__ __forceinline__ float geluf(float x){
    return 0.5f*x*(1.0f+erff(x*0.70710678118654752f));
}

// ---------------- K1: mean + circular conv1d embedding ----------------
__global__ __launch_bounds__(128) void k_embed(const float* __restrict__ x_enc,
                                               const float* __restrict__ conv_w)
{
    int bn = blockIdx.x, b = bn / C_NN, n = bn % C_NN, t = threadIdx.x;
    __shared__ float red[128];
    __shared__ float xs[C_NL+2];
    float v = 0.f;
    if (t < C_NL) v = x_enc[(size_t)(b*C_NL + t)*C_NN + n];
    red[t] = v; __syncthreads();
    #pragma unroll
    for (int s = 64; s > 0; s >>= 1) { if (t < s) red[t] += red[t+s]; __syncthreads(); }
    float mean = red[0] * (1.f/C_NL);
    if (t == 0) g_mean[bn] = mean;
    if (t < C_NL) xs[t+1] = v - mean;
    __syncthreads();
    if (t == 0) { xs[0] = xs[C_NL]; xs[C_NL+1] = xs[1]; }
    __syncthreads();
    float w0 = conv_w[t*3], w1 = conv_w[t*3+1], w2 = conv_w[t*3+2];
    float* out = g_enc + (size_t)bn*C_NL*C_ND;
    #pragma unroll 4
    for (int l = 0; l < C_NL; l++)
        out[l*C_ND + t] = w0*xs[l] + w1*xs[l+1] + w2*xs[l+2];
}

// ---------------- pe = pe_raw^T @ pos_w^T + pos_b ----------------
__global__ __launch_bounds__(256) void k_pe(const float* __restrict__ pe_raw,
    const float* __restrict__ pos_w, const float* __restrict__ pos_b)
{
    int idx = blockIdx.x*256 + threadIdx.x;
    if (idx >= C_NN*C_ND) return;
    int n = idx >> 7, d = idx & 127;
    g_pe[idx] = pe_raw[n]*pos_w[d*3] + pe_raw[C_NN+n]*pos_w[d*3+1]
              + pe_raw[2*C_NN+n]*pos_w[d*3+2] + pos_b[d];
}

// ---------------- LayerNorm (warp per 128-row) ----------------
__global__ __launch_bounds__(256) void k_ln(const float* __restrict__ in,
    const float* __restrict__ ga, const float* __restrict__ be, float* __restrict__ out)
{
    int row = blockIdx.x*8 + (threadIdx.x>>5), lane = threadIdx.x & 31;
    float4 x = *(const float4*)(in + (size_t)row*C_ND + lane*4);
    float s = x.x+x.y+x.z+x.w;
    #pragma unroll
    for (int o=16;o;o>>=1) s += __shfl_xor_sync(~0u, s, o);
    float mean = s*(1.f/128.f);
    float dx=x.x-mean, dy=x.y-mean, dz=x.z-mean, dw=x.w-mean;
    float sq = dx*dx+dy*dy+dz*dz+dw*dw;
    #pragma unroll
    for (int o=16;o;o>>=1) sq += __shfl_xor_sync(~0u, sq, o);
    float rstd = rsqrtf(sq*(1.f/128.f) + 1e-5f);
    float4 g = *(const float4*)(ga + lane*4), bb = *(const float4*)(be + lane*4);
    float4 o4 = make_float4(dx*rstd*g.x+bb.x, dy*rstd*g.y+bb.y,
                            dz*rstd*g.z+bb.z, dw*rstd*g.w+bb.w);
    *(float4*)(out + (size_t)row*C_ND + lane*4) = o4;
}

// ---------------- softmax over d=128 (with *d^-0.5) ----------------
__global__ __launch_bounds__(256) void k_softmax_d(float* __restrict__ buf)
{
    int row = blockIdx.x*8 + (threadIdx.x>>5), lane = threadIdx.x & 31;
    float* p = buf + (size_t)row*C_ND + lane*4;
    float4 x = *(const float4*)p;
    float m = fmaxf(fmaxf(x.x,x.y), fmaxf(x.z,x.w));
    #pragma unroll
    for (int o=16;o;o>>=1) m = fmaxf(m, __shfl_xor_sync(~0u, m, o));
    float4 e = make_float4(expf(x.x-m), expf(x.y-m), expf(x.z-m), expf(x.w-m));
    float s = e.x+e.y+e.z+e.w;
    #pragma unroll
    for (int o=16;o;o>>=1) s += __shfl_xor_sync(~0u, s, o);
    float sc = 0.08838834764831845f / s;
    e.x*=sc; e.y*=sc; e.z*=sc; e.w*=sc;
    *(float4*)p = e;
}

// ---------------- softmax over L=48 (axis 1) ----------------
__global__ __launch_bounds__(128) void k_softmax_L(float* __restrict__ buf)
{
    int bn = blockIdx.x, d = threadIdx.x;
    float* p = buf + (size_t)bn*C_NL*C_ND + d;
    float v[C_NL], m = -1e30f;
    #pragma unroll
    for (int l=0;l<C_NL;l++){ v[l]=p[l*C_ND]; m=fmaxf(m,v[l]); }
    float s = 0.f;
    #pragma unroll
    for (int l=0;l<C_NL;l++){ v[l]=expf(v[l]-m); s+=v[l]; }
    float inv = 1.f/s;
    #pragma unroll
    for (int l=0;l<C_NL;l++) p[l*C_ND] = v[l]*inv;
}

// ---------------- generic tiled SGEMM ----------------
// EPI: 0 store | 1 gelu(x+bias) | 2 C += x+bias | 3 C += x
#define TBK 16
#define SP 132
template<bool TRANSB, int EPI>
__global__ __launch_bounds__(256) void sgemm(
    const float* __restrict__ A, const float* __restrict__ Bm,
    float* __restrict__ C, const float* __restrict__ bias,
    int M, int N, int K)
{
    __shared__ float As[TBK*SP];
    __shared__ float Bs[TBK*SP];
    const int tid = threadIdx.x, ty = tid>>4, tx = tid&15;
    const int rowBase = blockIdx.x*128, colBase = blockIdx.y*128;
    float acc[8][8];
    #pragma unroll
    for (int i=0;i<8;i++)
        #pragma unroll
        for (int j=0;j<8;j++) acc[i][j]=0.f;
    const int ar = tid>>2, ac = (tid&3)<<2;
    const int numT = (K+TBK-1)/TBK;
    for (int kt=0; kt<numT; kt++){
        const int k0 = kt*TBK;
        #pragma unroll
        for (int hh=0; hh<2; hh++){
            int row = rowBase + ar + hh*64, kg = k0 + ac;
            float4 av = make_float4(0,0,0,0);
            if (row < M){
                const float* ap = A + (size_t)row*K + kg;
                if (kg+3 < K) av = *(const float4*)ap;
                else { if(kg<K)av.x=ap[0]; if(kg+1<K)av.y=ap[1]; if(kg+2<K)av.z=ap[2]; }
            }
            As[(ac+0)*SP+ar+hh*64]=av.x; As[(ac+1)*SP+ar+hh*64]=av.y;
            As[(ac+2)*SP+ar+hh*64]=av.z; As[(ac+3)*SP+ar+hh*64]=av.w;
        }
        if (!TRANSB){
            #pragma unroll
            for (int hh=0; hh<2; hh++){
                int kr = (tid>>5) + hh*8, c4 = (tid&31)<<2, kg = k0+kr;
                float4 bv = make_float4(0,0,0,0);
                if (kg < K) bv = *(const float4*)(Bm + (size_t)kg*N + colBase + c4);
                *(float4*)&Bs[kr*SP + c4] = bv;
            }
        } else {
            #pragma unroll
            for (int hh=0; hh<2; hh++){
                int nn = (tid>>2) + hh*64, k4 = (tid&3)<<2, kg = k0+k4;
                float4 bv = make_float4(0,0,0,0);
                const float* bp = Bm + (size_t)(colBase+nn)*K + kg;
                if (kg+3 < K) bv = *(const float4*)bp;
                else { if(kg<K)bv.x=bp[0]; if(kg+1<K)bv.y=bp[1]; if(kg+2<K)bv.z=bp[2]; }
                Bs[(k4+0)*SP+nn]=bv.x; Bs[(k4+1)*SP+nn]=bv.y;
                Bs[(k4+2)*SP+nn]=bv.z; Bs[(k4+3)*SP+nn]=bv.w;
            }
        }
        __syncthreads();
        #pragma unroll
        for (int kk=0; kk<TBK; kk++){
            float4 a0 = *(const float4*)&As[kk*SP + ty*8];
            float4 a1 = *(const float4*)&As[kk*SP + ty*8 + 4];
            float4 b0 = *(const float4*)&Bs[kk*SP + tx*8];
            float4 b1 = *(const float4*)&Bs[kk*SP + tx*8 + 4];
            float av[8]={a0.x,a0.y,a0.z,a0.w,a1.x,a1.y,a1.z,a1.w};
            float bv[8]={b0.x,b0.y,b0.z,b0.w,b1.x,b1.y,b1.z,b1.w};
            #pragma unroll
            for (int i=0;i<8;i++)
                #pragma unroll
                for (int j=0;j<8;j++) acc[i][j] = fmaf(av[i], bv[j], acc[i][j]);
        }
        __syncthreads();
    }
    #pragma unroll
    for (int i=0;i<8;i++){
        int row = rowBase + ty*8 + i;
        if (row >= M) continue;
        float* cp = C + (size_t)row*N + colBase + tx*8;
        #pragma unroll
        for (int jj=0; jj<2; jj++){
            float4 vv = make_float4(acc[i][jj*4],acc[i][jj*4+1],acc[i][jj*4+2],acc[i][jj*4+3]);
            if (EPI == 0){ *(float4*)(cp+jj*4) = vv; }
            else if (EPI == 1){
                const float* bp = bias + colBase + tx*8 + jj*4;
                vv.x=geluf(vv.x+bp[0]); vv.y=geluf(vv.y+bp[1]);
                vv.z=geluf(vv.z+bp[2]); vv.w=geluf(vv.w+bp[3]);
                *(float4*)(cp+jj*4) = vv;
            } else if (EPI == 2){
                const float* bp = bias + colBase + tx*8 + jj*4;
                float4 c0 = *(float4*)(cp+jj*4);
                c0.x+=vv.x+bp[0]; c0.y+=vv.y+bp[1]; c0.z+=vv.z+bp[2]; c0.w+=vv.w+bp[3];
                *(float4*)(cp+jj*4) = c0;
            } else {
                float4 c0 = *(float4*)(cp+jj*4);
                c0.x+=vv.x; c0.y+=vv.y; c0.z+=vv.z; c0.w+=vv.w;
                *(float4*)(cp+jj*4) = c0;
            }
        }
    }
}

// ---------------- fused linear-attention core per bn ----------------
// ctx = kk^T @ v (128x128, k=48); att0 = q @ ctx (48x128)
#define SM_ATTN ((2*48*132 + 128*132)*4)
__global__ __launch_bounds__(256) void k_attn()
{
    extern __shared__ float sm[];
    float* s_k = sm;                // 48x132 (kk, later q)
    float* s_v = sm + 48*132;       // 48x132
    float* s_c = sm + 2*48*132;     // 128x132 (ctx)
    const int bn = blockIdx.x, tid = threadIdx.x;
    const float* kb = g_kk + (size_t)bn*C_NL*C_ND;
    const float* vb = g_v  + (size_t)bn*C_NL*C_ND;
    for (int i = tid; i < (C_NL*C_ND)/4; i += 256){
        int e = i<<2, r = e>>7, c = e&127;
        *(float4*)&s_k[r*132+c] = *(const float4*)(kb+e);
        *(float4*)&s_v[r*132+c] = *(const float4*)(vb+e);
    }
    __syncthreads();
    // ctx tile: thread (ty,tx) computes 8x8
    const int ty = tid>>4, tx = tid&15;
    float acc[8][8];
    #pragma unroll
    for (int i=0;i<8;i++)
        #pragma unroll
        for (int j=0;j<8;j++) acc[i][j]=0.f;
    #pragma unroll 4
    for (int l=0;l<C_NL;l++){
        float4 a0 = *(const float4*)&s_k[l*132+ty*8];
        float4 a1 = *(const float4*)&s_k[l*132+ty*8+4];
        float4 b0 = *(const float4*)&s_v[l*132+tx*8];
        float4 b1 = *(const float4*)&s_v[l*132+tx*8+4];
        float av[8]={a0.x,a0.y,a0.z,a0.w,a1.x,a1.y,a1.z,a1.w};
        float bv[8]={b0.x,b0.y,b0.z,b0.w,b1.x,b1.y,b1.z,b1.w};
        #pragma unroll
        for (int i=0;i<8;i++)
            #pragma unroll
            for (int j=0;j<8;j++) acc[i][j] = fmaf(av[i], bv[j], acc[i][j]);
    }
    __syncthreads();      // everyone done reading s_k
    #pragma unroll
    for (int i=0;i<8;i++)
        #pragma unroll
        for (int j=0;j<8;j++) s_c[(ty*8+i)*132 + tx*8+j] = acc[i][j];
    // load q into s_k
    const float* qb = g_q + (size_t)bn*C_NL*C_ND;
    for (int i = tid; i < (C_NL*C_ND)/4; i += 256){
        int e = i<<2, r = e>>7, c = e&127;
        *(float4*)&s_k[r*132+c] = *(const float4*)(qb+e);
    }
    __syncthreads();
    // att0: warp w handles l = w, w+8, ...; lane covers 4 cols
    const int lane = tid&31, warp = tid>>5;
    float* ob = g_att0 + (size_t)bn*C_NL*C_ND;
    for (int l = warp; l < C_NL; l += 8){
        float4 a4 = make_float4(0,0,0,0);
        #pragma unroll 4
        for (int d=0; d<C_ND; d+=4){
            float4 q4 = *(const float4*)&s_k[l*132+d];
            float4 c0 = *(const float4*)&s_c[(d+0)*132 + lane*4];
            float4 c1 = *(const float4*)&s_c[(d+1)*132 + lane*4];
            float4 c2 = *(const float4*)&s_c[(d+2)*132 + lane*4];
            float4 c3 = *(const float4*)&s_c[(d+3)*132 + lane*4];
            a4.x += q4.x*c0.x + q4.y*c1.x + q4.z*c2.x + q4.w*c3.x;
            a4.y += q4.x*c0.y + q4.y*c1.y + q4.z*c2.y + q4.w*c3.y;
            a4.z += q4.x*c0.z + q4.y*c1.z + q4.z*c2.z + q4.w*c3.z;
            a4.w += q4.x*c0.w + q4.y*c1.w + q4.z*c2.w + q4.w*c3.w;
        }
        *(float4*)(ob + l*C_ND + lane*4) = a4;
    }
}

// ---------------- permute enc -> nf (N, BL, d) ----------------
__global__ __launch_bounds__(32) void k_permute()
{
    int r = blockIdx.x;                  // bn*48 + l
    int bn = r / C_NL, l = r % C_NL;
    int b = bn / C_NN, n = bn % C_NN;
    const float4* src = (const float4*)(g_enc + (size_t)r*C_ND);
    float4* dst = (float4*)(g_nf + ((size_t)n*C_BL + b*C_NL + l)*C_ND);
    dst[threadIdx.x] = src[threadIdx.x];
}

// ---------------- grouped per-node GEMM: res[n] = agg[n](96x128) @ pw[n](128x128)
#define SM_GRP ((128*132 + 96*128)*4)
__global__ __launch_bounds__(256) void k_group()
{
    extern __shared__ float sm[];
    float* s_w = sm;              // 128x132
    float* s_a = sm + 128*132;    // 96x128
    const int n = blockIdx.x, tid = threadIdx.x;
    const float* wb = g_pw + (size_t)n*C_ND*C_ND;
    const float* ab = g_agg + (size_t)n*C_BL*C_ND;
    for (int i = tid; i < (C_ND*C_ND)/4; i += 256){
        int e = i<<2, r = e>>7, c = e&127;
        *(float4*)&s_w[r*132+c] = *(const float4*)(wb+e);
    }
    for (int i = tid; i < (C_BL*C_ND)/4; i += 256)
        ((float4*)s_a)[i] = ((const float4*)ab)[i];
    __syncthreads();
    const int ty = tid>>4, tx = tid&15;    // rows ty*6.., cols tx*8..
    float acc[6][8];
    #pragma unroll
    for (int i=0;i<6;i++)
        #pragma unroll
        for (int j=0;j<8;j++) acc[i][j]=0.f;
    #pragma unroll 4
    for (int k=0;k<C_ND;k++){
        float4 b0 = *(const float4*)&s_w[k*132 + tx*8];
        float4 b1 = *(const float4*)&s_w[k*132 + tx*8+4];
        float bv[8]={b0.x,b0.y,b0.z,b0.w,b1.x,b1.y,b1.z,b1.w};
        #pragma unroll
        for (int i=0;i<6;i++){
            float a = s_a[(ty*6+i)*C_ND + k];
            #pragma unroll
            for (int j=0;j<8;j++) acc[i][j] = fmaf(a, bv[j], acc[i][j]);
        }
    }
    float* ob = g_res + (size_t)n*C_BL*C_ND;
    #pragma unroll
    for (int i=0;i<6;i++){
        #pragma unroll
        for (int jj=0;jj<2;jj++){
            float4 vv = make_float4(acc[i][jj*4],acc[i][jj*4+1],acc[i][jj*4+2],acc[i][jj*4+3]);
            *(float4*)(ob + (ty*6+i)*C_ND + tx*8 + jj*4) = vv;
        }
    }
}

// ---------------- GroupNorm stats: per (bl, group) over 32ch x 3000 nodes ----
__global__ __launch_bounds__(256) void k_gnred()
{
    int bl = blockIdx.x>>2, g = blockIdx.x&3;
    int base = bl*C_ND + g*32;
    float s = 0.f, ss = 0.f;
    for (int i = threadIdx.x; i < C_NN*32; i += 256){
        int n = i>>5, o = i&31;
        float v = g_res[(size_t)n*C_BL*C_ND + base + o];
        s += v; ss += v*v;
    }
    __shared__ float r1[256], r2[256];
    r1[threadIdx.x]=s; r2[threadIdx.x]=ss; __syncthreads();
    for (int st=128; st>0; st>>=1){
        if (threadIdx.x < st){ r1[threadIdx.x]+=r1[threadIdx.x+st]; r2[threadIdx.x]+=r2[threadIdx.x+st]; }
        __syncthreads();
    }
    if (threadIdx.x == 0){
        float mean = r1[0]/(C_NN*32.0f);
        float var = r2[0]/(C_NN*32.0f) - mean*mean;
        g_gmu[blockIdx.x] = mean;
        g_grs[blockIdx.x] = rsqrtf(var + 1e-5f);
    }
}

// ---------------- final fused: GN-apply, p2+silu, p1, +mean ----------------
__global__ __launch_bounds__(128) void k_final(
    const float* __restrict__ gn_g, const float* __restrict__ gn_b,
    const float* __restrict__ p2_w, const float* __restrict__ p2_b,
    const float* __restrict__ p1_w, const float* __restrict__ p1_b,
    float* __restrict__ out)
{
    int bn = blockIdx.x, b = bn / C_NN, n = bn % C_NN;
    int lane = threadIdx.x & 31, warp = threadIdx.x >> 5;
    __shared__ float s_s[C_NL];
    int d0 = lane*4, g = d0 >> 5;
    float4 gg = *(const float4*)(gn_g + d0);
    float4 gb = *(const float4*)(gn_b + d0);
    float4 pw = *(const float4*)(p2_w + d0);
    float p2b = p2_b[0];
    for (int l = warp; l < C_NL; l += 4){
        int bl = b*C_NL + l;
        float mu = g_gmu[bl*4 + g], rs = g_grs[bl*4 + g];
        float4 x = *(const float4*)(g_res + (size_t)n*C_BL*C_ND + bl*C_ND + d0);
        float dot = ((x.x-mu)*rs*gg.x+gb.x)*pw.x + ((x.y-mu)*rs*gg.y+gb.y)*pw.y
                  + ((x.z-mu)*rs*gg.z+gb.z)*pw.z + ((x.w-mu)*rs*gg.w+gb.w)*pw.w;
        #pragma unroll
        for (int o=16;o;o>>=1) dot += __shfl_xor_sync(~0u, dot, o);
        if (lane == 0){
            float sv = dot + p2b;
            s_s[l] = sv / (1.f + expf(-sv));
        }
    }
    __syncthreads();
    if (threadIdx.x < C_NLOUT){
        float acc = p1_b[threadIdx.x];
        #pragma unroll
        for (int l=0;l<C_NL;l++) acc = fmaf(p1_w[threadIdx.x*C_NL + l], s_s[l], acc);
        out[(size_t)b*C_NLOUT*C_NN + threadIdx.x*C_NN + n] = acc + g_mean[bn];
    }
}

// ---------------- driver ----------------
extern "C" void kernel_launch(void* const* d_in, const int* in_sizes, int n_in,
                              void* d_out, int out_size)
{
    const float* x_enc = (const float*)d_in[0];
    const float* adj   = (const float*)d_in[1];
    const float* pe_raw= (const float*)d_in[2];
    const float* conv_w= (const float*)d_in[3];
    const float* pos_w = (const float*)d_in[4];
    const float* pos_b = (const float*)d_in[5];
    const float* wq    = (const float*)d_in[6];
    const float* wk    = (const float*)d_in[7];
    const float* wv    = (const float*)d_in[8];
    const float* wo    = (const float*)d_in[9];
    const float* ln1_g = (const float*)d_in[10];
    const float* ln1_b = (const float*)d_in[11];
    const float* ff_w1 = (const float*)d_in[12];
    const float* ff_b1 = (const float*)d_in[13];
    const float* ff_w2 = (const float*)d_in[14];
    const float* ff_b2 = (const float*)d_in[15];
    const float* ln2_g = (const float*)d_in[16];
    const float* ln2_b = (const float*)d_in[17];
    const float* wpool = (const float*)d_in[18];
    const float* gn_g  = (const float*)d_in[19];
    const float* gn_b  = (const float*)d_in[20];
    const float* p2_w  = (const float*)d_in[21];
    const float* p2_b  = (const float*)d_in[22];
    const float* p1_w  = (const float*)d_in[23];
    const float* p1_b  = (const float*)d_in[24];
    float* out = (float*)d_out;

    cudaFuncSetAttribute(k_attn,  cudaFuncAttributeMaxDynamicSharedMemorySize, SM_ATTN);
    cudaFuncSetAttribute(k_group, cudaFuncAttributeMaxDynamicSharedMemorySize, SM_GRP);

    float *penc, *ph, *pq, *pkk, *pv, *patt0, *pff, *pnf, *pagg, *ppe, *ppe2, *ppw;
    cudaGetSymbolAddress((void**)&penc,  g_enc);
    cudaGetSymbolAddress((void**)&ph,    g_h);
    cudaGetSymbolAddress((void**)&pq,    g_q);
    cudaGetSymbolAddress((void**)&pkk,   g_kk);
    cudaGetSymbolAddress((void**)&pv,    g_v);
    cudaGetSymbolAddress((void**)&patt0, g_att0);
    cudaGetSymbolAddress((void**)&pff,   g_ff);
    cudaGetSymbolAddress((void**)&pnf,   g_nf);
    cudaGetSymbolAddress((void**)&pagg,  g_agg);
    cudaGetSymbolAddress((void**)&ppe,   g_pe);
    cudaGetSymbolAddress((void**)&ppe2,  g_pe2);
    cudaGetSymbolAddress((void**)&ppw,   g_pw);

    k_embed<<<C_BN, 128>>>(x_enc, conv_w);
    k_pe<<<(C_NN*C_ND + 255)/256, 256>>>(pe_raw, pos_w, pos_b);
    k_ln<<<C_ROWS/8, 256>>>(penc, ln1_g, ln1_b, ph);

    dim3 gP(C_ROWS/128, 1);
    sgemm<true,0><<<gP, 256>>>(ph, wq, pq,  nullptr, C_ROWS, 128, 128);
    sgemm<true,0><<<gP, 256>>>(ph, wk, pkk, nullptr, C_ROWS, 128, 128);
    sgemm<true,0><<<gP, 256>>>(ph, wv, pv,  nullptr, C_ROWS, 128, 128);
    k_softmax_d<<<C_ROWS/8, 256>>>(pq);
    k_softmax_L<<<C_BN, 128>>>(pkk);
    k_attn<<<C_BN, 256, SM_ATTN>>>();
    sgemm<true,3><<<gP, 256>>>(patt0, wo, penc, nullptr, C_ROWS, 128, 128);

    k_ln<<<C_ROWS/8, 256>>>(penc, ln2_g, ln2_b, ph);
    sgemm<true,1><<<dim3(C_ROWS/128, 4), 256>>>(ph, ff_w1, pff, ff_b1, C_ROWS, 512, 128);
    sgemm<true,2><<<gP, 256>>>(pff, ff_w2, penc, ff_b2, C_ROWS, 128, 512);

    k_permute<<<C_ROWS, 32>>>();
    sgemm<false,0><<<dim3(24, 96), 256>>>(adj, pnf, pagg, nullptr, C_NN, C_BL*C_ND, C_NN);
    sgemm<false,0><<<dim3(24, 1),  256>>>(adj, ppe, ppe2, nullptr, C_NN, 128, C_NN);
    sgemm<false,0><<<dim3(24, 128),256>>>(ppe2, wpool, ppw, nullptr, C_NN, 128*128, 128);
    k_group<<<C_NN, 256, SM_GRP>>>();
    k_gnred<<<C_BL*4, 256>>>();
    k_final<<<C_BN, 128>>>(gn_g, gn_b, p2_w, p2_b, p1_w, p1_b, out);
}

// round 6
// speedup vs baseline: 1.3599x; 1.3599x over previous
#include <cuda_runtime.h>
#include <cuda_bf16.h>
#include <math.h>
#include <stdint.h>

#define C_NB 2
#define C_NL 48
#define C_NN 3000
#define C_ND 128
#define C_NLOUT 24
#define C_BN (C_NB*C_NN)
#define C_ROWS (C_BN*C_NL)
#define C_BL (C_NB*C_NL)
#define KPAD 3008
#define MPAD 3072
#define NCOL (C_BL*C_ND)   // 12288
#define KP 9024            // 3 * KPAD (split-K3)
#define NCK (KP/32)        // 282

// ---------------- device-global scratch ----------------
__device__ float g_mean[C_BN];
__device__ float g_enc [C_ROWS*C_ND];
__device__ float g_h   [C_ROWS*C_ND];
__device__ float g_q   [C_ROWS*C_ND];
__device__ float g_kk  [C_ROWS*C_ND];
__device__ float g_v   [C_ROWS*C_ND];
__device__ float g_att0[C_ROWS*C_ND];
__device__ float g_ff  [C_ROWS*512];
__device__ float g_agg [(size_t)C_NN*NCOL];
__device__ float g_pe  [C_NN*C_ND];
__device__ float g_pe2 [C_NN*C_ND];
__device__ float g_pw  [(size_t)C_NN*C_ND*C_ND];
__device__ float g_res [(size_t)C_NN*NCOL];
__device__ float g_gmu [C_BL*4];
__device__ float g_grs [C_BL*4];
__device__ __nv_bfloat16 g_a2[(size_t)MPAD*KP];
__device__ __nv_bfloat16 g_b2[(size_t)NCOL*KP];

__device__ __forceinline__ float geluf(float x){
    return 0.5f*x*(1.0f+erff(x*0.70710678118654752f));
}
__device__ __forceinline__ uint32_t smem_u32(const void* p){
    uint32_t a;
    asm("{ .reg .u64 t; cvta.to.shared.u64 t, %1; cvt.u32.u64 %0, t; }" : "=r"(a) : "l"(p));
    return a;
}
#define CP_ASYNC16(dst, src) asm volatile("cp.async.cg.shared.global [%0], [%1], 16;" :: "r"(dst), "l"(src))
#define CP_COMMIT() asm volatile("cp.async.commit_group;" ::: "memory")
#define CP_WAIT(n)  asm volatile("cp.async.wait_group %0;" :: "n"(n) : "memory")
#define LDSM4(r0,r1,r2,r3,addr) \
    asm volatile("ldmatrix.sync.aligned.m8n8.x4.shared.b16 {%0,%1,%2,%3}, [%4];" \
        : "=r"(r0),"=r"(r1),"=r"(r2),"=r"(r3) : "r"(addr))
#define MMA16816(d, a, b) asm volatile( \
    "mma.sync.aligned.m16n8k16.row.col.f32.bf16.bf16.f32 " \
    "{%0,%1,%2,%3}, {%4,%5,%6,%7}, {%8,%9}, {%0,%1,%2,%3};" \
    : "+f"((d)[0]),"+f"((d)[1]),"+f"((d)[2]),"+f"((d)[3]) \
    : "r"((a)[0]),"r"((a)[1]),"r"((a)[2]),"r"((a)[3]), "r"((b)[0]),"r"((b)[1]))

// ---------------- K1: mean + circular conv1d embedding ----------------
__global__ __launch_bounds__(128) void k_embed(const float* __restrict__ x_enc,
                                               const float* __restrict__ conv_w)
{
    int bn = blockIdx.x, b = bn / C_NN, n = bn % C_NN, t = threadIdx.x;
    __shared__ float red[128];
    __shared__ float xs[C_NL+2];
    float v = 0.f;
    if (t < C_NL) v = x_enc[(size_t)(b*C_NL + t)*C_NN + n];
    red[t] = v; __syncthreads();
    #pragma unroll
    for (int s = 64; s > 0; s >>= 1) { if (t < s) red[t] += red[t+s]; __syncthreads(); }
    float mean = red[0] * (1.f/C_NL);
    if (t == 0) g_mean[bn] = mean;
    if (t < C_NL) xs[t+1] = v - mean;
    __syncthreads();
    if (t == 0) { xs[0] = xs[C_NL]; xs[C_NL+1] = xs[1]; }
    __syncthreads();
    float w0 = conv_w[t*3], w1 = conv_w[t*3+1], w2 = conv_w[t*3+2];
    float* out = g_enc + (size_t)bn*C_NL*C_ND;
    #pragma unroll 4
    for (int l = 0; l < C_NL; l++)
        out[l*C_ND + t] = w0*xs[l] + w1*xs[l+1] + w2*xs[l+2];
}

// ---------------- pe = pe_raw^T @ pos_w^T + pos_b ----------------
__global__ __launch_bounds__(256) void k_pe(const float* __restrict__ pe_raw,
    const float* __restrict__ pos_w, const float* __restrict__ pos_b)
{
    int idx = blockIdx.x*256 + threadIdx.x;
    if (idx >= C_NN*C_ND) return;
    int n = idx >> 7, d = idx & 127;
    g_pe[idx] = pe_raw[n]*pos_w[d*3] + pe_raw[C_NN+n]*pos_w[d*3+1]
              + pe_raw[2*C_NN+n]*pos_w[d*3+2] + pos_b[d];
}

// ---------------- LayerNorm ----------------
__global__ __launch_bounds__(256) void k_ln(const float* __restrict__ in,
    const float* __restrict__ ga, const float* __restrict__ be, float* __restrict__ out)
{
    int row = blockIdx.x*8 + (threadIdx.x>>5), lane = threadIdx.x & 31;
    float4 x = *(const float4*)(in + (size_t)row*C_ND + lane*4);
    float s = x.x+x.y+x.z+x.w;
    #pragma unroll
    for (int o=16;o;o>>=1) s += __shfl_xor_sync(~0u, s, o);
    float mean = s*(1.f/128.f);
    float dx=x.x-mean, dy=x.y-mean, dz=x.z-mean, dw=x.w-mean;
    float sq = dx*dx+dy*dy+dz*dz+dw*dw;
    #pragma unroll
    for (int o=16;o;o>>=1) sq += __shfl_xor_sync(~0u, sq, o);
    float rstd = rsqrtf(sq*(1.f/128.f) + 1e-5f);
    float4 g = *(const float4*)(ga + lane*4), bb = *(const float4*)(be + lane*4);
    float4 o4 = make_float4(dx*rstd*g.x+bb.x, dy*rstd*g.y+bb.y,
                            dz*rstd*g.z+bb.z, dw*rstd*g.w+bb.w);
    *(float4*)(out + (size_t)row*C_ND + lane*4) = o4;
}

// ---------------- softmax over d ----------------
__global__ __launch_bounds__(256) void k_softmax_d(float* __restrict__ buf)
{
    int row = blockIdx.x*8 + (threadIdx.x>>5), lane = threadIdx.x & 31;
    float* p = buf + (size_t)row*C_ND + lane*4;
    float4 x = *(const float4*)p;
    float m = fmaxf(fmaxf(x.x,x.y), fmaxf(x.z,x.w));
    #pragma unroll
    for (int o=16;o;o>>=1) m = fmaxf(m, __shfl_xor_sync(~0u, m, o));
    float4 e = make_float4(expf(x.x-m), expf(x.y-m), expf(x.z-m), expf(x.w-m));
    float s = e.x+e.y+e.z+e.w;
    #pragma unroll
    for (int o=16;o;o>>=1) s += __shfl_xor_sync(~0u, s, o);
    float sc = 0.08838834764831845f / s;
    e.x*=sc; e.y*=sc; e.z*=sc; e.w*=sc;
    *(float4*)p = e;
}

// ---------------- softmax over L ----------------
__global__ __launch_bounds__(128) void k_softmax_L(float* __restrict__ buf)
{
    int bn = blockIdx.x, d = threadIdx.x;
    float* p = buf + (size_t)bn*C_NL*C_ND + d;
    float v[C_NL], m = -1e30f;
    #pragma unroll
    for (int l=0;l<C_NL;l++){ v[l]=p[l*C_ND]; m=fmaxf(m,v[l]); }
    float s = 0.f;
    #pragma unroll
    for (int l=0;l<C_NL;l++){ v[l]=expf(v[l]-m); s+=v[l]; }
    float inv = 1.f/s;
    #pragma unroll
    for (int l=0;l<C_NL;l++) p[l*C_ND] = v[l]*inv;
}

// ---------------- tiled fp32 SGEMM ----------------
#define TBK 16
#define SP 132
template<bool TRANSB, int EPI>
__global__ __launch_bounds__(256) void sgemm(
    const float* __restrict__ A, const float* __restrict__ Bm,
    float* __restrict__ C, const float* __restrict__ bias,
    int M, int N, int K)
{
    __shared__ float As[TBK*SP];
    __shared__ float Bs[TBK*SP];
    const int tid = threadIdx.x, ty = tid>>4, tx = tid&15;
    const int rowBase = blockIdx.x*128, colBase = blockIdx.y*128;
    float acc[8][8];
    #pragma unroll
    for (int i=0;i<8;i++)
        #pragma unroll
        for (int j=0;j<8;j++) acc[i][j]=0.f;
    const int ar = tid>>2, ac = (tid&3)<<2;
    const int numT = (K+TBK-1)/TBK;
    for (int kt=0; kt<numT; kt++){
        const int k0 = kt*TBK;
        #pragma unroll
        for (int hh=0; hh<2; hh++){
            int row = rowBase + ar + hh*64, kg = k0 + ac;
            float4 av = make_float4(0,0,0,0);
            if (row < M){
                const float* ap = A + (size_t)row*K + kg;
                if (kg+3 < K) av = *(const float4*)ap;
                else { if(kg<K)av.x=ap[0]; if(kg+1<K)av.y=ap[1]; if(kg+2<K)av.z=ap[2]; }
            }
            As[(ac+0)*SP+ar+hh*64]=av.x; As[(ac+1)*SP+ar+hh*64]=av.y;
            As[(ac+2)*SP+ar+hh*64]=av.z; As[(ac+3)*SP+ar+hh*64]=av.w;
        }
        if (!TRANSB){
            #pragma unroll
            for (int hh=0; hh<2; hh++){
                int kr = (tid>>5) + hh*8, c4 = (tid&31)<<2, kg = k0+kr;
                float4 bv = make_float4(0,0,0,0);
                if (kg < K) bv = *(const float4*)(Bm + (size_t)kg*N + colBase + c4);
                *(float4*)&Bs[kr*SP + c4] = bv;
            }
        } else {
            #pragma unroll
            for (int hh=0; hh<2; hh++){
                int nn = (tid>>2) + hh*64, k4 = (tid&3)<<2, kg = k0+k4;
                float4 bv = make_float4(0,0,0,0);
                const float* bp = Bm + (size_t)(colBase+nn)*K + kg;
                if (kg+3 < K) bv = *(const float4*)bp;
                else { if(kg<K)bv.x=bp[0]; if(kg+1<K)bv.y=bp[1]; if(kg+2<K)bv.z=bp[2]; }
                Bs[(k4+0)*SP+nn]=bv.x; Bs[(k4+1)*SP+nn]=bv.y;
                Bs[(k4+2)*SP+nn]=bv.z; Bs[(k4+3)*SP+nn]=bv.w;
            }
        }
        __syncthreads();
        #pragma unroll
        for (int kk=0; kk<TBK; kk++){
            float4 a0 = *(const float4*)&As[kk*SP + ty*8];
            float4 a1 = *(const float4*)&As[kk*SP + ty*8 + 4];
            float4 b0 = *(const float4*)&Bs[kk*SP + tx*8];
            float4 b1 = *(const float4*)&Bs[kk*SP + tx*8 + 4];
            float av[8]={a0.x,a0.y,a0.z,a0.w,a1.x,a1.y,a1.z,a1.w};
            float bv[8]={b0.x,b0.y,b0.z,b0.w,b1.x,b1.y,b1.z,b1.w};
            #pragma unroll
            for (int i=0;i<8;i++)
                #pragma unroll
                for (int j=0;j<8;j++) acc[i][j] = fmaf(av[i], bv[j], acc[i][j]);
        }
        __syncthreads();
    }
    #pragma unroll
    for (int i=0;i<8;i++){
        int row = rowBase + ty*8 + i;
        if (row >= M) continue;
        float* cp = C + (size_t)row*N + colBase + tx*8;
        #pragma unroll
        for (int jj=0; jj<2; jj++){
            float4 vv = make_float4(acc[i][jj*4],acc[i][jj*4+1],acc[i][jj*4+2],acc[i][jj*4+3]);
            if (EPI == 0){ *(float4*)(cp+jj*4) = vv; }
            else if (EPI == 1){
                const float* bp = bias + colBase + tx*8 + jj*4;
                vv.x=geluf(vv.x+bp[0]); vv.y=geluf(vv.y+bp[1]);
                vv.z=geluf(vv.z+bp[2]); vv.w=geluf(vv.w+bp[3]);
                *(float4*)(cp+jj*4) = vv;
            } else if (EPI == 2){
                const float* bp = bias + colBase + tx*8 + jj*4;
                float4 c0 = *(float4*)(cp+jj*4);
                c0.x+=vv.x+bp[0]; c0.y+=vv.y+bp[1]; c0.z+=vv.z+bp[2]; c0.w+=vv.w+bp[3];
                *(float4*)(cp+jj*4) = c0;
            } else {
                float4 c0 = *(float4*)(cp+jj*4);
                c0.x+=vv.x; c0.y+=vv.y; c0.z+=vv.z; c0.w+=vv.w;
                *(float4*)(cp+jj*4) = c0;
            }
        }
    }
}

// ---------------- fused linear-attention core per bn ----------------
#define SM_ATTN ((2*48*132 + 128*132)*4)
__global__ __launch_bounds__(256) void k_attn()
{
    extern __shared__ float sm[];
    float* s_k = sm;
    float* s_v = sm + 48*132;
    float* s_c = sm + 2*48*132;
    const int bn = blockIdx.x, tid = threadIdx.x;
    const float* kb = g_kk + (size_t)bn*C_NL*C_ND;
    const float* vb = g_v  + (size_t)bn*C_NL*C_ND;
    for (int i = tid; i < (C_NL*C_ND)/4; i += 256){
        int e = i<<2, r = e>>7, c = e&127;
        *(float4*)&s_k[r*132+c] = *(const float4*)(kb+e);
        *(float4*)&s_v[r*132+c] = *(const float4*)(vb+e);
    }
    __syncthreads();
    const int ty = tid>>4, tx = tid&15;
    float acc[8][8];
    #pragma unroll
    for (int i=0;i<8;i++)
        #pragma unroll
        for (int j=0;j<8;j++) acc[i][j]=0.f;
    #pragma unroll 4
    for (int l=0;l<C_NL;l++){
        float4 a0 = *(const float4*)&s_k[l*132+ty*8];
        float4 a1 = *(const float4*)&s_k[l*132+ty*8+4];
        float4 b0 = *(const float4*)&s_v[l*132+tx*8];
        float4 b1 = *(const float4*)&s_v[l*132+tx*8+4];
        float av[8]={a0.x,a0.y,a0.z,a0.w,a1.x,a1.y,a1.z,a1.w};
        float bv[8]={b0.x,b0.y,b0.z,b0.w,b1.x,b1.y,b1.z,b1.w};
        #pragma unroll
        for (int i=0;i<8;i++)
            #pragma unroll
            for (int j=0;j<8;j++) acc[i][j] = fmaf(av[i], bv[j], acc[i][j]);
    }
    __syncthreads();
    #pragma unroll
    for (int i=0;i<8;i++)
        #pragma unroll
        for (int j=0;j<8;j++) s_c[(ty*8+i)*132 + tx*8+j] = acc[i][j];
    const float* qb = g_q + (size_t)bn*C_NL*C_ND;
    for (int i = tid; i < (C_NL*C_ND)/4; i += 256){
        int e = i<<2, r = e>>7, c = e&127;
        *(float4*)&s_k[r*132+c] = *(const float4*)(qb+e);
    }
    __syncthreads();
    const int lane = tid&31, warp = tid>>5;
    float* ob = g_att0 + (size_t)bn*C_NL*C_ND;
    for (int l = warp; l < C_NL; l += 8){
        float4 a4 = make_float4(0,0,0,0);
        #pragma unroll 4
        for (int d=0; d<C_ND; d+=4){
            float4 q4 = *(const float4*)&s_k[l*132+d];
            float4 c0 = *(const float4*)&s_c[(d+0)*132 + lane*4];
            float4 c1 = *(const float4*)&s_c[(d+1)*132 + lane*4];
            float4 c2 = *(const float4*)&s_c[(d+2)*132 + lane*4];
            float4 c3 = *(const float4*)&s_c[(d+3)*132 + lane*4];
            a4.x += q4.x*c0.x + q4.y*c1.x + q4.z*c2.x + q4.w*c3.x;
            a4.y += q4.x*c0.y + q4.y*c1.y + q4.z*c2.y + q4.w*c3.y;
            a4.z += q4.x*c0.z + q4.y*c1.z + q4.z*c2.z + q4.w*c3.z;
            a4.w += q4.x*c0.w + q4.y*c1.w + q4.z*c2.w + q4.w*c3.w;
        }
        *(float4*)(ob + l*C_ND + lane*4) = a4;
    }
}

// ---------------- split adj -> A2 = [Ah | Ah | Al], rows padded to MPAD ------
__global__ __launch_bounds__(256) void k_split_adj(const float* __restrict__ adj)
{
    size_t idx = (size_t)blockIdx.x*256 + threadIdx.x;
    if (idx >= (size_t)MPAD*KPAD) return;
    int m = (int)(idx / KPAD), k = (int)(idx % KPAD);
    float v = (m < C_NN && k < C_NN) ? adj[(size_t)m*C_NN + k] : 0.f;
    __nv_bfloat16 h = __float2bfloat16(v);
    __nv_bfloat16 l = __float2bfloat16(v - __bfloat162float(h));
    __nv_bfloat16* p = g_a2 + (size_t)m*KP + k;
    p[0] = h; p[KPAD] = h; p[2*KPAD] = l;
}

// -------- build B2^T = [Bh | Bl | Bh]: row c=(bl*128+d), col k=node ---------
__global__ __launch_bounds__(256) void k_bt()
{
    __shared__ float sm[32][33];
    int n0 = blockIdx.x*32, d0 = blockIdx.y*32, bl = blockIdx.z;
    int b = bl / C_NL, l = bl % C_NL;
    int tx = threadIdx.x & 31, ty = threadIdx.x >> 5;
    #pragma unroll
    for (int s=0;s<4;s++){
        int n = n0 + ty + s*8;
        float v = 0.f;
        if (n < C_NN) v = g_enc[((size_t)(b*C_NN + n)*C_NL + l)*C_ND + d0 + tx];
        sm[ty+s*8][tx] = v;
    }
    __syncthreads();
    #pragma unroll
    for (int s=0;s<4;s++){
        int dl = ty + s*8;
        float v = sm[tx][dl];
        __nv_bfloat16 h = __float2bfloat16(v);
        __nv_bfloat16 lo = __float2bfloat16(v - __bfloat162float(h));
        __nv_bfloat16* p = g_b2 + (size_t)(bl*C_ND + d0 + dl)*KP + n0 + tx;
        p[0] = h; p[KPAD] = lo; p[2*KPAD] = h;
    }
}

// ---------------- HMMA bf16 split-K3 GEMM: g_agg = adj @ nf ----------------
__global__ __launch_bounds__(256) void k_hgemm()
{
    __shared__ __nv_bfloat16 As[2][128*40];
    __shared__ __nv_bfloat16 Bs[2][128*40];
    const int tid = threadIdx.x;
    const int mBase = blockIdx.x*128, cBase = blockIdx.y*128;
    const __nv_bfloat16* pA = g_a2 + (size_t)mBase*KP;
    const __nv_bfloat16* pB = g_b2 + (size_t)cBase*KP;
    const int warp = tid>>5, lane = tid&31;
    const int wm = warp&3, wn = warp>>2;
    float acc[2][8][4];
    #pragma unroll
    for (int i=0;i<2;i++)
        #pragma unroll
        for (int j=0;j<8;j++)
            #pragma unroll
            for (int q=0;q<4;q++) acc[i][j][q] = 0.f;

    // prefetch thread mapping: 1024 x 16B per chunk, 4 per thread
    #define PREFETCH(ck, buf) do { \
        int _k0 = (ck)*32; \
        _Pragma("unroll") \
        for (int _t=0; _t<4; _t++){ \
            int _j = _t*256 + tid; \
            int _jj = _j & 511; \
            int _r = _jj>>2, _seg = _jj&3; \
            const __nv_bfloat16* _src = ((_j < 512) ? pA : pB) + (size_t)_r*KP + _k0 + _seg*8; \
            uint32_t _dst = smem_u32(((_j < 512) ? &As[buf][0] : &Bs[buf][0]) + _r*40 + _seg*8); \
            CP_ASYNC16(_dst, _src); \
        } \
        CP_COMMIT(); \
    } while(0)

    PREFETCH(0, 0);
    for (int ck = 0; ck < NCK; ck++){
        if (ck + 1 < NCK){ PREFETCH(ck+1, (ck+1)&1); CP_WAIT(1); }
        else             { CP_WAIT(0); }
        __syncthreads();
        const __nv_bfloat16* as = &As[ck&1][0];
        const __nv_bfloat16* bs = &Bs[ck&1][0];
        #pragma unroll
        for (int ks=0; ks<2; ks++){
            const int kc = ks*16;
            uint32_t a[2][4], bfr[8][2];
            #pragma unroll
            for (int mt=0; mt<2; mt++){
                int row = wm*32 + mt*16 + (lane&7) + ((lane>>3)&1)*8;
                int col = kc + (lane>>4)*8;
                uint32_t ad = smem_u32(as + row*40 + col);
                LDSM4(a[mt][0], a[mt][1], a[mt][2], a[mt][3], ad);
            }
            #pragma unroll
            for (int p=0; p<4; p++){
                int row = wn*64 + p*16 + (lane>>4)*8 + (lane&7);
                int col = kc + ((lane>>3)&1)*8;
                uint32_t bd = smem_u32(bs + row*40 + col);
                uint32_t r0,r1,r2,r3;
                LDSM4(r0,r1,r2,r3, bd);
                bfr[p*2][0]=r0; bfr[p*2][1]=r1; bfr[p*2+1][0]=r2; bfr[p*2+1][1]=r3;
            }
            #pragma unroll
            for (int mt=0; mt<2; mt++)
                #pragma unroll
                for (int nt=0; nt<8; nt++)
                    MMA16816(acc[mt][nt], a[mt], bfr[nt]);
        }
        __syncthreads();
    }
    // epilogue
    const int g = lane>>2, tg = lane&3;
    #pragma unroll
    for (int mt=0; mt<2; mt++){
        int r0 = mBase + wm*32 + mt*16 + g;
        #pragma unroll
        for (int nt=0; nt<8; nt++){
            int c0 = cBase + wn*64 + nt*8 + tg*2;
            if (r0 < C_NN)
                *(float2*)&g_agg[(size_t)r0*NCOL + c0] = make_float2(acc[mt][nt][0], acc[mt][nt][1]);
            if (r0+8 < C_NN)
                *(float2*)&g_agg[(size_t)(r0+8)*NCOL + c0] = make_float2(acc[mt][nt][2], acc[mt][nt][3]);
        }
    }
    #undef PREFETCH
}

// ---------------- grouped per-node GEMM ----------------
#define SM_GRP ((128*132 + 96*128)*4)
__global__ __launch_bounds__(256) void k_group()
{
    extern __shared__ float sm[];
    float* s_w = sm;
    float* s_a = sm + 128*132;
    const int n = blockIdx.x, tid = threadIdx.x;
    const float* wb = g_pw + (size_t)n*C_ND*C_ND;
    const float* ab = g_agg + (size_t)n*C_BL*C_ND;
    for (int i = tid; i < (C_ND*C_ND)/4; i += 256){
        int e = i<<2, r = e>>7, c = e&127;
        *(float4*)&s_w[r*132+c] = *(const float4*)(wb+e);
    }
    for (int i = tid; i < (C_BL*C_ND)/4; i += 256)
        ((float4*)s_a)[i] = ((const float4*)ab)[i];
    __syncthreads();
    const int ty = tid>>4, tx = tid&15;
    float acc[6][8];
    #pragma unroll
    for (int i=0;i<6;i++)
        #pragma unroll
        for (int j=0;j<8;j++) acc[i][j]=0.f;
    #pragma unroll 4
    for (int k=0;k<C_ND;k++){
        float4 b0 = *(const float4*)&s_w[k*132 + tx*8];
        float4 b1 = *(const float4*)&s_w[k*132 + tx*8+4];
        float bv[8]={b0.x,b0.y,b0.z,b0.w,b1.x,b1.y,b1.z,b1.w};
        #pragma unroll
        for (int i=0;i<6;i++){
            float a = s_a[(ty*6+i)*C_ND + k];
            #pragma unroll
            for (int j=0;j<8;j++) acc[i][j] = fmaf(a, bv[j], acc[i][j]);
        }
    }
    float* ob = g_res + (size_t)n*C_BL*C_ND;
    #pragma unroll
    for (int i=0;i<6;i++){
        #pragma unroll
        for (int jj=0;jj<2;jj++){
            float4 vv = make_float4(acc[i][jj*4],acc[i][jj*4+1],acc[i][jj*4+2],acc[i][jj*4+3]);
            *(float4*)(ob + (ty*6+i)*C_ND + tx*8 + jj*4) = vv;
        }
    }
}

// ---------------- GroupNorm stats ----------------
__global__ __launch_bounds__(256) void k_gnred()
{
    int bl = blockIdx.x>>2, g = blockIdx.x&3;
    int base = bl*C_ND + g*32;
    float s = 0.f, ss = 0.f;
    for (int i = threadIdx.x; i < C_NN*32; i += 256){
        int n = i>>5, o = i&31;
        float v = g_res[(size_t)n*C_BL*C_ND + base + o];
        s += v; ss += v*v;
    }
    __shared__ float r1[256], r2[256];
    r1[threadIdx.x]=s; r2[threadIdx.x]=ss; __syncthreads();
    for (int st=128; st>0; st>>=1){
        if (threadIdx.x < st){ r1[threadIdx.x]+=r1[threadIdx.x+st]; r2[threadIdx.x]+=r2[threadIdx.x+st]; }
        __syncthreads();
    }
    if (threadIdx.x == 0){
        float mean = r1[0]/(C_NN*32.0f);
        float var = r2[0]/(C_NN*32.0f) - mean*mean;
        g_gmu[blockIdx.x] = mean;
        g_grs[blockIdx.x] = rsqrtf(var + 1e-5f);
    }
}

// ---------------- final fused ----------------
__global__ __launch_bounds__(128) void k_final(
    const float* __restrict__ gn_g, const float* __restrict__ gn_b,
    const float* __restrict__ p2_w, const float* __restrict__ p2_b,
    const float* __restrict__ p1_w, const float* __restrict__ p1_b,
    float* __restrict__ out)
{
    int bn = blockIdx.x, b = bn / C_NN, n = bn % C_NN;
    int lane = threadIdx.x & 31, warp = threadIdx.x >> 5;
    __shared__ float s_s[C_NL];
    int d0 = lane*4, g = d0 >> 5;
    float4 gg = *(const float4*)(gn_g + d0);
    float4 gb = *(const float4*)(gn_b + d0);
    float4 pw = *(const float4*)(p2_w + d0);
    float p2b = p2_b[0];
    for (int l = warp; l < C_NL; l += 4){
        int bl = b*C_NL + l;
        float mu = g_gmu[bl*4 + g], rs = g_grs[bl*4 + g];
        float4 x = *(const float4*)(g_res + (size_t)n*C_BL*C_ND + bl*C_ND + d0);
        float dot = ((x.x-mu)*rs*gg.x+gb.x)*pw.x + ((x.y-mu)*rs*gg.y+gb.y)*pw.y
                  + ((x.z-mu)*rs*gg.z+gb.z)*pw.z + ((x.w-mu)*rs*gg.w+gb.w)*pw.w;
        #pragma unroll
        for (int o=16;o;o>>=1) dot += __shfl_xor_sync(~0u, dot, o);
        if (lane == 0){
            float sv = dot + p2b;
            s_s[l] = sv / (1.f + expf(-sv));
        }
    }
    __syncthreads();
    if (threadIdx.x < C_NLOUT){
        float acc = p1_b[threadIdx.x];
        #pragma unroll
        for (int l=0;l<C_NL;l++) acc = fmaf(p1_w[threadIdx.x*C_NL + l], s_s[l], acc);
        out[(size_t)b*C_NLOUT*C_NN + threadIdx.x*C_NN + n] = acc + g_mean[bn];
    }
}

// ---------------- driver ----------------
extern "C" void kernel_launch(void* const* d_in, const int* in_sizes, int n_in,
                              void* d_out, int out_size)
{
    const float* x_enc = (const float*)d_in[0];
    const float* adj   = (const float*)d_in[1];
    const float* pe_raw= (const float*)d_in[2];
    const float* conv_w= (const float*)d_in[3];
    const float* pos_w = (const float*)d_in[4];
    const float* pos_b = (const float*)d_in[5];
    const float* wq    = (const float*)d_in[6];
    const float* wk    = (const float*)d_in[7];
    const float* wv    = (const float*)d_in[8];
    const float* wo    = (const float*)d_in[9];
    const float* ln1_g = (const float*)d_in[10];
    const float* ln1_b = (const float*)d_in[11];
    const float* ff_w1 = (const float*)d_in[12];
    const float* ff_b1 = (const float*)d_in[13];
    const float* ff_w2 = (const float*)d_in[14];
    const float* ff_b2 = (const float*)d_in[15];
    const float* ln2_g = (const float*)d_in[16];
    const float* ln2_b = (const float*)d_in[17];
    const float* wpool = (const float*)d_in[18];
    const float* gn_g  = (const float*)d_in[19];
    const float* gn_b  = (const float*)d_in[20];
    const float* p2_w  = (const float*)d_in[21];
    const float* p2_b  = (const float*)d_in[22];
    const float* p1_w  = (const float*)d_in[23];
    const float* p1_b  = (const float*)d_in[24];
    float* out = (float*)d_out;

    cudaFuncSetAttribute(k_attn,  cudaFuncAttributeMaxDynamicSharedMemorySize, SM_ATTN);
    cudaFuncSetAttribute(k_group, cudaFuncAttributeMaxDynamicSharedMemorySize, SM_GRP);

    float *penc, *ph, *pq, *pkk, *pv, *patt0, *pff, *ppe, *ppe2, *ppw;
    cudaGetSymbolAddress((void**)&penc,  g_enc);
    cudaGetSymbolAddress((void**)&ph,    g_h);
    cudaGetSymbolAddress((void**)&pq,    g_q);
    cudaGetSymbolAddress((void**)&pkk,   g_kk);
    cudaGetSymbolAddress((void**)&pv,    g_v);
    cudaGetSymbolAddress((void**)&patt0, g_att0);
    cudaGetSymbolAddress((void**)&pff,   g_ff);
    cudaGetSymbolAddress((void**)&ppe,   g_pe);
    cudaGetSymbolAddress((void**)&ppe2,  g_pe2);
    cudaGetSymbolAddress((void**)&ppw,   g_pw);

    k_embed<<<C_BN, 128>>>(x_enc, conv_w);
    k_pe<<<(C_NN*C_ND + 255)/256, 256>>>(pe_raw, pos_w, pos_b);
    k_split_adj<<<(int)(((size_t)MPAD*KPAD + 255)/256), 256>>>(adj);
    k_ln<<<C_ROWS/8, 256>>>(penc, ln1_g, ln1_b, ph);

    dim3 gP(C_ROWS/128, 1);
    sgemm<true,0><<<gP, 256>>>(ph, wq, pq,  nullptr, C_ROWS, 128, 128);
    sgemm<true,0><<<gP, 256>>>(ph, wk, pkk, nullptr, C_ROWS, 128, 128);
    sgemm<true,0><<<gP, 256>>>(ph, wv, pv,  nullptr, C_ROWS, 128, 128);
    k_softmax_d<<<C_ROWS/8, 256>>>(pq);
    k_softmax_L<<<C_BN, 128>>>(pkk);
    k_attn<<<C_BN, 256, SM_ATTN>>>();
    sgemm<true,3><<<gP, 256>>>(patt0, wo, penc, nullptr, C_ROWS, 128, 128);

    k_ln<<<C_ROWS/8, 256>>>(penc, ln2_g, ln2_b, ph);
    sgemm<true,1><<<dim3(C_ROWS/128, 4), 256>>>(ph, ff_w1, pff, ff_b1, C_ROWS, 512, 128);
    sgemm<true,2><<<gP, 256>>>(pff, ff_w2, penc, ff_b2, C_ROWS, 128, 512);

    k_bt<<<dim3(KPAD/32, C_ND/32, C_BL), 256>>>();
    k_hgemm<<<dim3(MPAD/128, NCOL/128), 256>>>();

    sgemm<false,0><<<dim3(24, 1),  256>>>(adj, ppe, ppe2, nullptr, C_NN, 128, C_NN);
    sgemm<false,0><<<dim3(24, 128),256>>>(ppe2, wpool, ppw, nullptr, C_NN, 128*128, 128);
    k_group<<<C_NN, 256, SM_GRP>>>();
    k_gnred<<<C_BL*4, 256>>>();
    k_final<<<C_BN, 128>>>(gn_g, gn_b, p2_w, p2_b, p1_w, p1_b, out);
}

// round 9
// speedup vs baseline: 1.5744x; 1.1577x over previous
#include <cuda_runtime.h>
#include <cuda_bf16.h>
#include <math.h>
#include <stdint.h>

#define C_NB 2
#define C_NL 48
#define C_NN 3000
#define C_ND 128
#define C_NLOUT 24
#define C_BN (C_NB*C_NN)
#define C_ROWS (C_BN*C_NL)
#define C_BL (C_NB*C_NL)
#define KPAD 3008
#define MPAD 3072
#define NCOL (C_BL*C_ND)   // 12288
#define KP 9024            // 3 * KPAD (split-K3 for adj GEMM)

// ---------------- device-global scratch (aliased to cut footprint) ----------
// g_agg aliases g_ff (FF mid is dead before spatial GEMM writes agg)
// g_res aliases g_q  (q is dead after k_attn)
// g_ffp aliases g_b2 (FF2 packed input is dead before k_bt writes B2)
__device__ float g_mean[C_BN];
__device__ float g_enc [C_ROWS*C_ND];
__device__ float g_h   [C_ROWS*C_ND];
__device__ float g_q   [C_ROWS*C_ND];          // also: g_res
__device__ float g_kk  [C_ROWS*C_ND];
__device__ float g_v   [C_ROWS*C_ND];
__device__ float g_att0[C_ROWS*C_ND];
__device__ float g_ff  [C_ROWS*512];           // also: g_agg
__device__ float g_pe  [C_NN*C_ND];
__device__ float g_pe2 [C_NN*C_ND];
__device__ float g_pw  [(size_t)C_NN*C_ND*C_ND];
__device__ float g_gmu [C_BL*4];
__device__ float g_grs [C_BL*4];
__device__ __nv_bfloat16 g_a2 [(size_t)MPAD*KP];
__device__ __nv_bfloat16 g_b2 [(size_t)C_ROWS*1536];  // max(NCOL*KP, FF2 pack)
__device__ __nv_bfloat16 g_ap [(size_t)C_ROWS*384];
__device__ __nv_bfloat16 g_bp [(size_t)16384*384];

__device__ __forceinline__ float geluf(float x){
    return 0.5f*x*(1.0f+erff(x*0.70710678118654752f));
}
__device__ __forceinline__ uint32_t smem_u32(const void* p){
    uint32_t a;
    asm("{ .reg .u64 t; cvta.to.shared.u64 t, %1; cvt.u32.u64 %0, t; }" : "=r"(a) : "l"(p));
    return a;
}
#define CP_ASYNC16(dst, src) asm volatile("cp.async.cg.shared.global [%0], [%1], 16;" :: "r"(dst), "l"(src))
#define CP_COMMIT() asm volatile("cp.async.commit_group;" ::: "memory")
#define CP_WAIT(n)  asm volatile("cp.async.wait_group %0;" :: "n"(n) : "memory")
#define LDSM4(r0,r1,r2,r3,addr) \
    asm volatile("ldmatrix.sync.aligned.m8n8.x4.shared.b16 {%0,%1,%2,%3}, [%4];" \
        : "=r"(r0),"=r"(r1),"=r"(r2),"=r"(r3) : "r"(addr))
#define MMA16816(d, a, b) asm volatile( \
    "mma.sync.aligned.m16n8k16.row.col.f32.bf16.bf16.f32 " \
    "{%0,%1,%2,%3}, {%4,%5,%6,%7}, {%8,%9}, {%0,%1,%2,%3};" \
    : "+f"((d)[0]),"+f"((d)[1]),"+f"((d)[2]),"+f"((d)[3]) \
    : "r"((a)[0]),"r"((a)[1]),"r"((a)[2]),"r"((a)[3]), "r"((b)[0]),"r"((b)[1]))

// ---------------- K1: mean + circular conv1d embedding ----------------
__global__ __launch_bounds__(128) void k_embed(const float* __restrict__ x_enc,
                                               const float* __restrict__ conv_w)
{
    int bn = blockIdx.x, b = bn / C_NN, n = bn % C_NN, t = threadIdx.x;
    __shared__ float red[128];
    __shared__ float xs[C_NL+2];
    float v = 0.f;
    if (t < C_NL) v = x_enc[(size_t)(b*C_NL + t)*C_NN + n];
    red[t] = v; __syncthreads();
    #pragma unroll
    for (int s = 64; s > 0; s >>= 1) { if (t < s) red[t] += red[t+s]; __syncthreads(); }
    float mean = red[0] * (1.f/C_NL);
    if (t == 0) g_mean[bn] = mean;
    if (t < C_NL) xs[t+1] = v - mean;
    __syncthreads();
    if (t == 0) { xs[0] = xs[C_NL]; xs[C_NL+1] = xs[1]; }
    __syncthreads();
    float w0 = conv_w[t*3], w1 = conv_w[t*3+1], w2 = conv_w[t*3+2];
    float* out = g_enc + (size_t)bn*C_NL*C_ND;
    #pragma unroll 4
    for (int l = 0; l < C_NL; l++)
        out[l*C_ND + t] = w0*xs[l] + w1*xs[l+1] + w2*xs[l+2];
}

// ---------------- pe projection ----------------
__global__ __launch_bounds__(256) void k_pe(const float* __restrict__ pe_raw,
    const float* __restrict__ pos_w, const float* __restrict__ pos_b)
{
    int idx = blockIdx.x*256 + threadIdx.x;
    if (idx >= C_NN*C_ND) return;
    int n = idx >> 7, d = idx & 127;
    g_pe[idx] = pe_raw[n]*pos_w[d*3] + pe_raw[C_NN+n]*pos_w[d*3+1]
              + pe_raw[2*C_NN+n]*pos_w[d*3+2] + pos_b[d];
}

// ---------------- LayerNorm ----------------
__global__ __launch_bounds__(256) void k_ln(const float* __restrict__ in,
    const float* __restrict__ ga, const float* __restrict__ be, float* __restrict__ out)
{
    int row = blockIdx.x*8 + (threadIdx.x>>5), lane = threadIdx.x & 31;
    float4 x = *(const float4*)(in + (size_t)row*C_ND + lane*4);
    float s = x.x+x.y+x.z+x.w;
    #pragma unroll
    for (int o=16;o;o>>=1) s += __shfl_xor_sync(~0u, s, o);
    float mean = s*(1.f/128.f);
    float dx=x.x-mean, dy=x.y-mean, dz=x.z-mean, dw=x.w-mean;
    float sq = dx*dx+dy*dy+dz*dz+dw*dw;
    #pragma unroll
    for (int o=16;o;o>>=1) sq += __shfl_xor_sync(~0u, sq, o);
    float rstd = rsqrtf(sq*(1.f/128.f) + 1e-5f);
    float4 g = *(const float4*)(ga + lane*4), bb = *(const float4*)(be + lane*4);
    float4 o4 = make_float4(dx*rstd*g.x+bb.x, dy*rstd*g.y+bb.y,
                            dz*rstd*g.z+bb.z, dw*rstd*g.w+bb.w);
    *(float4*)(out + (size_t)row*C_ND + lane*4) = o4;
}

// ---------------- softmax over d ----------------
__global__ __launch_bounds__(256) void k_softmax_d(float* __restrict__ buf)
{
    int row = blockIdx.x*8 + (threadIdx.x>>5), lane = threadIdx.x & 31;
    float* p = buf + (size_t)row*C_ND + lane*4;
    float4 x = *(const float4*)p;
    float m = fmaxf(fmaxf(x.x,x.y), fmaxf(x.z,x.w));
    #pragma unroll
    for (int o=16;o;o>>=1) m = fmaxf(m, __shfl_xor_sync(~0u, m, o));
    float4 e = make_float4(expf(x.x-m), expf(x.y-m), expf(x.z-m), expf(x.w-m));
    float s = e.x+e.y+e.z+e.w;
    #pragma unroll
    for (int o=16;o;o>>=1) s += __shfl_xor_sync(~0u, s, o);
    float sc = 0.08838834764831845f / s;
    e.x*=sc; e.y*=sc; e.z*=sc; e.w*=sc;
    *(float4*)p = e;
}

// ---------------- softmax over L ----------------
__global__ __launch_bounds__(128) void k_softmax_L(float* __restrict__ buf)
{
    int bn = blockIdx.x, d = threadIdx.x;
    float* p = buf + (size_t)bn*C_NL*C_ND + d;
    float v[C_NL], m = -1e30f;
    #pragma unroll
    for (int l=0;l<C_NL;l++){ v[l]=p[l*C_ND]; m=fmaxf(m,v[l]); }
    float s = 0.f;
    #pragma unroll
    for (int l=0;l<C_NL;l++){ v[l]=expf(v[l]-m); s+=v[l]; }
    float inv = 1.f/s;
    #pragma unroll
    for (int l=0;l<C_NL;l++) p[l*C_ND] = v[l]*inv;
}

// ---------------- tiled fp32 SGEMM (only small pe2 GEMM now) ----------------
#define TBK 16
#define SP 132
__global__ __launch_bounds__(256) void sgemm_nn(
    const float* __restrict__ A, const float* __restrict__ Bm,
    float* __restrict__ C, int M, int N, int K)
{
    __shared__ float As[TBK*SP];
    __shared__ float Bs[TBK*SP];
    const int tid = threadIdx.x, ty = tid>>4, tx = tid&15;
    const int rowBase = blockIdx.x*128, colBase = blockIdx.y*128;
    float acc[8][8];
    #pragma unroll
    for (int i=0;i<8;i++)
        #pragma unroll
        for (int j=0;j<8;j++) acc[i][j]=0.f;
    const int ar = tid>>2, ac = (tid&3)<<2;
    const int numT = (K+TBK-1)/TBK;
    for (int kt=0; kt<numT; kt++){
        const int k0 = kt*TBK;
        #pragma unroll
        for (int hh=0; hh<2; hh++){
            int row = rowBase + ar + hh*64, kg = k0 + ac;
            float4 av = make_float4(0,0,0,0);
            if (row < M){
                const float* ap = A + (size_t)row*K + kg;
                if (kg+3 < K) av = *(const float4*)ap;
                else { if(kg<K)av.x=ap[0]; if(kg+1<K)av.y=ap[1]; if(kg+2<K)av.z=ap[2]; }
            }
            As[(ac+0)*SP+ar+hh*64]=av.x; As[(ac+1)*SP+ar+hh*64]=av.y;
            As[(ac+2)*SP+ar+hh*64]=av.z; As[(ac+3)*SP+ar+hh*64]=av.w;
        }
        #pragma unroll
        for (int hh=0; hh<2; hh++){
            int kr = (tid>>5) + hh*8, c4 = (tid&31)<<2, kg = k0+kr;
            float4 bv = make_float4(0,0,0,0);
            if (kg < K) bv = *(const float4*)(Bm + (size_t)kg*N + colBase + c4);
            *(float4*)&Bs[kr*SP + c4] = bv;
        }
        __syncthreads();
        #pragma unroll
        for (int kk=0; kk<TBK; kk++){
            float4 a0 = *(const float4*)&As[kk*SP + ty*8];
            float4 a1 = *(const float4*)&As[kk*SP + ty*8 + 4];
            float4 b0 = *(const float4*)&Bs[kk*SP + tx*8];
            float4 b1 = *(const float4*)&Bs[kk*SP + tx*8 + 4];
            float av[8]={a0.x,a0.y,a0.z,a0.w,a1.x,a1.y,a1.z,a1.w};
            float bv[8]={b0.x,b0.y,b0.z,b0.w,b1.x,b1.y,b1.z,b1.w};
            #pragma unroll
            for (int i=0;i<8;i++)
                #pragma unroll
                for (int j=0;j<8;j++) acc[i][j] = fmaf(av[i], bv[j], acc[i][j]);
        }
        __syncthreads();
    }
    #pragma unroll
    for (int i=0;i<8;i++){
        int row = rowBase + ty*8 + i;
        if (row >= M) continue;
        float* cp = C + (size_t)row*N + colBase + tx*8;
        #pragma unroll
        for (int jj=0; jj<2; jj++)
            *(float4*)(cp+jj*4) = make_float4(acc[i][jj*4],acc[i][jj*4+1],acc[i][jj*4+2],acc[i][jj*4+3]);
    }
}

// ---------------- fused linear-attention core per bn ----------------
#define SM_ATTN ((2*48*132 + 128*132)*4)
__global__ __launch_bounds__(256) void k_attn()
{
    extern __shared__ float sm[];
    float* s_k = sm;
    float* s_v = sm + 48*132;
    float* s_c = sm + 2*48*132;
    const int bn = blockIdx.x, tid = threadIdx.x;
    const float* kb = g_kk + (size_t)bn*C_NL*C_ND;
    const float* vb = g_v  + (size_t)bn*C_NL*C_ND;
    for (int i = tid; i < (C_NL*C_ND)/4; i += 256){
        int e = i<<2, r = e>>7, c = e&127;
        *(float4*)&s_k[r*132+c] = *(const float4*)(kb+e);
        *(float4*)&s_v[r*132+c] = *(const float4*)(vb+e);
    }
    __syncthreads();
    const int ty = tid>>4, tx = tid&15;
    float acc[8][8];
    #pragma unroll
    for (int i=0;i<8;i++)
        #pragma unroll
        for (int j=0;j<8;j++) acc[i][j]=0.f;
    #pragma unroll 4
    for (int l=0;l<C_NL;l++){
        float4 a0 = *(const float4*)&s_k[l*132+ty*8];
        float4 a1 = *(const float4*)&s_k[l*132+ty*8+4];
        float4 b0 = *(const float4*)&s_v[l*132+tx*8];
        float4 b1 = *(const float4*)&s_v[l*132+tx*8+4];
        float av[8]={a0.x,a0.y,a0.z,a0.w,a1.x,a1.y,a1.z,a1.w};
        float bv[8]={b0.x,b0.y,b0.z,b0.w,b1.x,b1.y,b1.z,b1.w};
        #pragma unroll
        for (int i=0;i<8;i++)
            #pragma unroll
            for (int j=0;j<8;j++) acc[i][j] = fmaf(av[i], bv[j], acc[i][j]);
    }
    __syncthreads();
    #pragma unroll
    for (int i=0;i<8;i++)
        #pragma unroll
        for (int j=0;j<8;j++) s_c[(ty*8+i)*132 + tx*8+j] = acc[i][j];
    const float* qb = g_q + (size_t)bn*C_NL*C_ND;
    for (int i = tid; i < (C_NL*C_ND)/4; i += 256){
        int e = i<<2, r = e>>7, c = e&127;
        *(float4*)&s_k[r*132+c] = *(const float4*)(qb+e);
    }
    __syncthreads();
    const int lane = tid&31, warp = tid>>5;
    float* ob = g_att0 + (size_t)bn*C_NL*C_ND;
    for (int l = warp; l < C_NL; l += 8){
        float4 a4 = make_float4(0,0,0,0);
        #pragma unroll 4
        for (int d=0; d<C_ND; d+=4){
            float4 q4 = *(const float4*)&s_k[l*132+d];
            float4 c0 = *(const float4*)&s_c[(d+0)*132 + lane*4];
            float4 c1 = *(const float4*)&s_c[(d+1)*132 + lane*4];
            float4 c2 = *(const float4*)&s_c[(d+2)*132 + lane*4];
            float4 c3 = *(const float4*)&s_c[(d+3)*132 + lane*4];
            a4.x += q4.x*c0.x + q4.y*c1.x + q4.z*c2.x + q4.w*c3.x;
            a4.y += q4.x*c0.y + q4.y*c1.y + q4.z*c2.y + q4.w*c3.y;
            a4.z += q4.x*c0.z + q4.y*c1.z + q4.z*c2.z + q4.w*c3.z;
            a4.w += q4.x*c0.w + q4.y*c1.w + q4.z*c2.w + q4.w*c3.w;
        }
        *(float4*)(ob + l*C_ND + lane*4) = a4;
    }
}

// ---------------- split adj -> A2 = [Ah | Ah | Al] ----------------
__global__ __launch_bounds__(256) void k_split_adj(const float* __restrict__ adj)
{
    size_t idx = (size_t)blockIdx.x*256 + threadIdx.x;
    if (idx >= (size_t)MPAD*KPAD) return;
    int m = (int)(idx / KPAD), k = (int)(idx % KPAD);
    float v = (m < C_NN && k < C_NN) ? adj[(size_t)m*C_NN + k] : 0.f;
    __nv_bfloat16 h = __float2bfloat16(v);
    __nv_bfloat16 l = __float2bfloat16(v - __bfloat162float(h));
    __nv_bfloat16* p = g_a2 + (size_t)m*KP + k;
    p[0] = h; p[KPAD] = h; p[2*KPAD] = l;
}

// -------- build B2^T = [Bh | Bl | Bh] into given buffer ----------------
__global__ __launch_bounds__(256) void k_bt(__nv_bfloat16* __restrict__ B2)
{
    __shared__ float sm[32][33];
    int n0 = blockIdx.x*32, d0 = blockIdx.y*32, bl = blockIdx.z;
    int b = bl / C_NL, l = bl % C_NL;
    int tx = threadIdx.x & 31, ty = threadIdx.x >> 5;
    #pragma unroll
    for (int s=0;s<4;s++){
        int n = n0 + ty + s*8;
        float v = 0.f;
        if (n < C_NN) v = g_enc[((size_t)(b*C_NN + n)*C_NL + l)*C_ND + d0 + tx];
        sm[ty+s*8][tx] = v;
    }
    __syncthreads();
    #pragma unroll
    for (int s=0;s<4;s++){
        int dl = ty + s*8;
        float v = sm[tx][dl];
        __nv_bfloat16 h = __float2bfloat16(v);
        __nv_bfloat16 lo = __float2bfloat16(v - __bfloat162float(h));
        __nv_bfloat16* p = B2 + (size_t)(bl*C_ND + d0 + dl)*KP + n0 + tx;
        p[0] = h; p[KPAD] = lo; p[2*KPAD] = h;
    }
}

// ---------------- pack activations A[M][K] -> Ap[Mpad][3K]=[Ah|Al|Ah] --------
__global__ __launch_bounds__(256) void k_packA(const float* __restrict__ A,
    __nv_bfloat16* __restrict__ Ap, int M, int K, int Mpad)
{
    size_t idx = (size_t)blockIdx.x*256 + threadIdx.x;
    if (idx >= (size_t)Mpad*K) return;
    int row = (int)(idx / K), k = (int)(idx % K);
    float v = (row < M) ? A[(size_t)row*K + k] : 0.f;
    __nv_bfloat16 h = __float2bfloat16(v);
    __nv_bfloat16 lo = __float2bfloat16(v - __bfloat162float(h));
    __nv_bfloat16* p = Ap + (size_t)row*3*K + k;
    p[0] = h; p[K] = lo; p[2*K] = h;
}

// ---------------- pack weights B[N][K] -> Bp[N][3K]=[Bh|Bh|Bl] --------------
__global__ __launch_bounds__(256) void k_packB(const float* __restrict__ B,
    __nv_bfloat16* __restrict__ Bp, int N, int K)
{
    int idx = blockIdx.x*256 + threadIdx.x;
    if (idx >= N*K) return;
    int n = idx / K, k = idx % K;
    float v = B[(size_t)n*K + k];
    __nv_bfloat16 h = __float2bfloat16(v);
    __nv_bfloat16 lo = __float2bfloat16(v - __bfloat162float(h));
    __nv_bfloat16* p = Bp + (size_t)n*3*K + k;
    p[0] = h; p[K] = h; p[2*K] = lo;
}

// --------- pack transposed weights W[K][N] -> Bp[N][3K]=[Bh|Bh|Bl] ----------
__global__ __launch_bounds__(256) void k_packBt(const float* __restrict__ W,
    __nv_bfloat16* __restrict__ Bp, int N, int K)
{
    int idx = blockIdx.x*256 + threadIdx.x;
    if (idx >= N*K) return;
    int n = idx / K, k = idx % K;
    float v = W[(size_t)k*N + n];
    __nv_bfloat16 h = __float2bfloat16(v);
    __nv_bfloat16 lo = __float2bfloat16(v - __bfloat162float(h));
    __nv_bfloat16* p = Bp + (size_t)n*3*K + k;
    p[0] = h; p[K] = h; p[2*K] = lo;
}

// ---------------- generic HMMA bf16 GEMM: C[M][N] (+)= A @ B^T --------------
// EPI: 0 store | 1 gelu(x+bias) | 2 C += x+bias | 3 C += x
template<int EPI>
__global__ __launch_bounds__(256) void hgemm(
    const __nv_bfloat16* __restrict__ A, const __nv_bfloat16* __restrict__ Bm,
    float* __restrict__ C, const float* __restrict__ bias,
    int Mreal, int N, int K)
{
    __shared__ __nv_bfloat16 As[2][128*40];
    __shared__ __nv_bfloat16 Bs[2][128*40];
    const int tid = threadIdx.x;
    const int mBase = blockIdx.x*128, cBase = blockIdx.y*128;
    const __nv_bfloat16* pA = A + (size_t)mBase*K;
    const __nv_bfloat16* pB = Bm + (size_t)cBase*K;
    const int warp = tid>>5, lane = tid&31;
    const int wm = warp&3, wn = warp>>2;
    float acc[2][8][4];
    #pragma unroll
    for (int i=0;i<2;i++)
        #pragma unroll
        for (int j=0;j<8;j++)
            #pragma unroll
            for (int q=0;q<4;q++) acc[i][j][q] = 0.f;

    #define PREFETCH(ck, buf) do { \
        int _k0 = (ck)*32; \
        _Pragma("unroll") \
        for (int _t=0; _t<4; _t++){ \
            int _j = _t*256 + tid; \
            int _jj = _j & 511; \
            int _r = _jj>>2, _seg = _jj&3; \
            const __nv_bfloat16* _src = ((_j < 512) ? pA : pB) + (size_t)_r*K + _k0 + _seg*8; \
            uint32_t _dst = smem_u32(((_j < 512) ? &As[buf][0] : &Bs[buf][0]) + _r*40 + _seg*8); \
            CP_ASYNC16(_dst, _src); \
        } \
        CP_COMMIT(); \
    } while(0)

    const int nck = K >> 5;
    PREFETCH(0, 0);
    for (int ck = 0; ck < nck; ck++){
        if (ck + 1 < nck){ PREFETCH(ck+1, (ck+1)&1); CP_WAIT(1); }
        else             { CP_WAIT(0); }
        __syncthreads();
        const __nv_bfloat16* as = &As[ck&1][0];
        const __nv_bfloat16* bs = &Bs[ck&1][0];
        #pragma unroll
        for (int ks=0; ks<2; ks++){
            const int kc = ks*16;
            uint32_t a[2][4], bfr[8][2];
            #pragma unroll
            for (int mt=0; mt<2; mt++){
                int row = wm*32 + mt*16 + (lane&7) + ((lane>>3)&1)*8;
                int col = kc + (lane>>4)*8;
                uint32_t ad = smem_u32(as + row*40 + col);
                LDSM4(a[mt][0], a[mt][1], a[mt][2], a[mt][3], ad);
            }
            #pragma unroll
            for (int p=0; p<4; p++){
                int row = wn*64 + p*16 + (lane>>4)*8 + (lane&7);
                int col = kc + ((lane>>3)&1)*8;
                uint32_t bd = smem_u32(bs + row*40 + col);
                uint32_t r0,r1,r2,r3;
                LDSM4(r0,r1,r2,r3, bd);
                bfr[p*2][0]=r0; bfr[p*2][1]=r1; bfr[p*2+1][0]=r2; bfr[p*2+1][1]=r3;
            }
            #pragma unroll
            for (int mt=0; mt<2; mt++)
                #pragma unroll
                for (int nt=0; nt<8; nt++)
                    MMA16816(acc[mt][nt], a[mt], bfr[nt]);
        }
        __syncthreads();
    }
    #undef PREFETCH

    const int g = lane>>2, tg = lane&3;
    #pragma unroll
    for (int mt=0; mt<2; mt++){
        int rbase = mBase + wm*32 + mt*16 + g;
        #pragma unroll
        for (int half=0; half<2; half++){
            int r = rbase + half*8;
            if (r >= Mreal) continue;
            #pragma unroll
            for (int nt=0; nt<8; nt++){
                int c0 = cBase + wn*64 + nt*8 + tg*2;
                float v0 = acc[mt][nt][half*2], v1 = acc[mt][nt][half*2+1];
                float* cp = &C[(size_t)r*N + c0];
                if (EPI == 0){
                    *(float2*)cp = make_float2(v0, v1);
                } else if (EPI == 1){
                    *(float2*)cp = make_float2(geluf(v0 + bias[c0]), geluf(v1 + bias[c0+1]));
                } else if (EPI == 2){
                    float2 c = *(float2*)cp;
                    *(float2*)cp = make_float2(c.x + v0 + bias[c0], c.y + v1 + bias[c0+1]);
                } else {
                    float2 c = *(float2*)cp;
                    *(float2*)cp = make_float2(c.x + v0, c.y + v1);
                }
            }
        }
    }
}

// ---------------- grouped per-node GEMM (agg=g_ff, res=g_q) ----------------
#define SM_GRP ((128*132 + 96*128)*4)
__global__ __launch_bounds__(256) void k_group()
{
    extern __shared__ float sm[];
    float* s_w = sm;
    float* s_a = sm + 128*132;
    const int n = blockIdx.x, tid = threadIdx.x;
    const float* wb = g_pw + (size_t)n*C_ND*C_ND;
    const float* ab = g_ff + (size_t)n*C_BL*C_ND;       // agg aliases g_ff
    for (int i = tid; i < (C_ND*C_ND)/4; i += 256){
        int e = i<<2, r = e>>7, c = e&127;
        *(float4*)&s_w[r*132+c] = *(const float4*)(wb+e);
    }
    for (int i = tid; i < (C_BL*C_ND)/4; i += 256)
        ((float4*)s_a)[i] = ((const float4*)ab)[i];
    __syncthreads();
    const int ty = tid>>4, tx = tid&15;
    float acc[6][8];
    #pragma unroll
    for (int i=0;i<6;i++)
        #pragma unroll
        for (int j=0;j<8;j++) acc[i][j]=0.f;
    #pragma unroll 4
    for (int k=0;k<C_ND;k++){
        float4 b0 = *(const float4*)&s_w[k*132 + tx*8];
        float4 b1 = *(const float4*)&s_w[k*132 + tx*8+4];
        float bv[8]={b0.x,b0.y,b0.z,b0.w,b1.x,b1.y,b1.z,b1.w};
        #pragma unroll
        for (int i=0;i<6;i++){
            float a = s_a[(ty*6+i)*C_ND + k];
            #pragma unroll
            for (int j=0;j<8;j++) acc[i][j] = fmaf(a, bv[j], acc[i][j]);
        }
    }
    float* ob = g_q + (size_t)n*C_BL*C_ND;              // res aliases g_q
    #pragma unroll
    for (int i=0;i<6;i++){
        #pragma unroll
        for (int jj=0;jj<2;jj++){
            float4 vv = make_float4(acc[i][jj*4],acc[i][jj*4+1],acc[i][jj*4+2],acc[i][jj*4+3]);
            *(float4*)(ob + (ty*6+i)*C_ND + tx*8 + jj*4) = vv;
        }
    }
}

// ---------------- GroupNorm stats (res = g_q) ----------------
__global__ __launch_bounds__(256) void k_gnred()
{
    int bl = blockIdx.x>>2, g = blockIdx.x&3;
    int base = bl*C_ND + g*32;
    float s = 0.f, ss = 0.f;
    for (int i = threadIdx.x; i < C_NN*32; i += 256){
        int n = i>>5, o = i&31;
        float v = g_q[(size_t)n*C_BL*C_ND + base + o];
        s += v; ss += v*v;
    }
    __shared__ float r1[256], r2[256];
    r1[threadIdx.x]=s; r2[threadIdx.x]=ss; __syncthreads();
    for (int st=128; st>0; st>>=1){
        if (threadIdx.x < st){ r1[threadIdx.x]+=r1[threadIdx.x+st]; r2[threadIdx.x]+=r2[threadIdx.x+st]; }
        __syncthreads();
    }
    if (threadIdx.x == 0){
        float mean = r1[0]/(C_NN*32.0f);
        float var = r2[0]/(C_NN*32.0f) - mean*mean;
        g_gmu[blockIdx.x] = mean;
        g_grs[blockIdx.x] = rsqrtf(var + 1e-5f);
    }
}

// ---------------- final fused (res = g_q) ----------------
__global__ __launch_bounds__(128) void k_final(
    const float* __restrict__ gn_g, const float* __restrict__ gn_b,
    const float* __restrict__ p2_w, const float* __restrict__ p2_b,
    const float* __restrict__ p1_w, const float* __restrict__ p1_b,
    float* __restrict__ out)
{
    int bn = blockIdx.x, b = bn / C_NN, n = bn % C_NN;
    int lane = threadIdx.x & 31, warp = threadIdx.x >> 5;
    __shared__ float s_s[C_NL];
    int d0 = lane*4, g = d0 >> 5;
    float4 gg = *(const float4*)(gn_g + d0);
    float4 gb = *(const float4*)(gn_b + d0);
    float4 pw = *(const float4*)(p2_w + d0);
    float p2b = p2_b[0];
    for (int l = warp; l < C_NL; l += 4){
        int bl = b*C_NL + l;
        float mu = g_gmu[bl*4 + g], rs = g_grs[bl*4 + g];
        float4 x = *(const float4*)(g_q + (size_t)n*C_BL*C_ND + bl*C_ND + d0);
        float dot = ((x.x-mu)*rs*gg.x+gb.x)*pw.x + ((x.y-mu)*rs*gg.y+gb.y)*pw.y
                  + ((x.z-mu)*rs*gg.z+gb.z)*pw.z + ((x.w-mu)*rs*gg.w+gb.w)*pw.w;
        #pragma unroll
        for (int o=16;o;o>>=1) dot += __shfl_xor_sync(~0u, dot, o);
        if (lane == 0){
            float sv = dot + p2b;
            s_s[l] = sv / (1.f + expf(-sv));
        }
    }
    __syncthreads();
    if (threadIdx.x < C_NLOUT){
        float acc = p1_b[threadIdx.x];
        #pragma unroll
        for (int l=0;l<C_NL;l++) acc = fmaf(p1_w[threadIdx.x*C_NL + l], s_s[l], acc);
        out[(size_t)b*C_NLOUT*C_NN + threadIdx.x*C_NN + n] = acc + g_mean[bn];
    }
}

// ---------------- driver ----------------
extern "C" void kernel_launch(void* const* d_in, const int* in_sizes, int n_in,
                              void* d_out, int out_size)
{
    const float* x_enc = (const float*)d_in[0];
    const float* adj   = (const float*)d_in[1];
    const float* pe_raw= (const float*)d_in[2];
    const float* conv_w= (const float*)d_in[3];
    const float* pos_w = (const float*)d_in[4];
    const float* pos_b = (const float*)d_in[5];
    const float* wq    = (const float*)d_in[6];
    const float* wk    = (const float*)d_in[7];
    const float* wv    = (const float*)d_in[8];
    const float* wo    = (const float*)d_in[9];
    const float* ln1_g = (const float*)d_in[10];
    const float* ln1_b = (const float*)d_in[11];
    const float* ff_w1 = (const float*)d_in[12];
    const float* ff_b1 = (const float*)d_in[13];
    const float* ff_w2 = (const float*)d_in[14];
    const float* ff_b2 = (const float*)d_in[15];
    const float* ln2_g = (const float*)d_in[16];
    const float* ln2_b = (const float*)d_in[17];
    const float* wpool = (const float*)d_in[18];
    const float* gn_g  = (const float*)d_in[19];
    const float* gn_b  = (const float*)d_in[20];
    const float* p2_w  = (const float*)d_in[21];
    const float* p2_b  = (const float*)d_in[22];
    const float* p1_w  = (const float*)d_in[23];
    const float* p1_b  = (const float*)d_in[24];
    float* out = (float*)d_out;

    cudaFuncSetAttribute(k_attn,  cudaFuncAttributeMaxDynamicSharedMemorySize, SM_ATTN);
    cudaFuncSetAttribute(k_group, cudaFuncAttributeMaxDynamicSharedMemorySize, SM_GRP);

    float *penc, *ph, *pq, *pkk, *pv, *patt0, *pff, *ppe, *ppe2, *ppw;
    __nv_bfloat16 *pa2, *pb2, *pap, *pbp;
    cudaGetSymbolAddress((void**)&penc,  g_enc);
    cudaGetSymbolAddress((void**)&ph,    g_h);
    cudaGetSymbolAddress((void**)&pq,    g_q);
    cudaGetSymbolAddress((void**)&pkk,   g_kk);
    cudaGetSymbolAddress((void**)&pv,    g_v);
    cudaGetSymbolAddress((void**)&patt0, g_att0);
    cudaGetSymbolAddress((void**)&pff,   g_ff);
    cudaGetSymbolAddress((void**)&ppe,   g_pe);
    cudaGetSymbolAddress((void**)&ppe2,  g_pe2);
    cudaGetSymbolAddress((void**)&ppw,   g_pw);
    cudaGetSymbolAddress((void**)&pa2,   g_a2);
    cudaGetSymbolAddress((void**)&pb2,   g_b2);
    cudaGetSymbolAddress((void**)&pap,   g_ap);
    cudaGetSymbolAddress((void**)&pbp,   g_bp);

    __nv_bfloat16* pffp = pb2;   // alias: FF2 packed input shares g_b2
    float* pagg = pff;           // alias: spatial agg shares g_ff

    const int APACK_G = (int)(((size_t)C_ROWS*128 + 255)/256);
    const int FFPACK_G = (int)(((size_t)C_ROWS*512 + 255)/256);

    k_embed<<<C_BN, 128>>>(x_enc, conv_w);
    k_pe<<<(C_NN*C_ND + 255)/256, 256>>>(pe_raw, pos_w, pos_b);
    k_split_adj<<<(int)(((size_t)MPAD*KPAD + 255)/256), 256>>>(adj);
    k_ln<<<C_ROWS/8, 256>>>(penc, ln1_g, ln1_b, ph);

    // q/k/v projections via HMMA split-K3
    k_packA<<<APACK_G, 256>>>(ph, pap, C_ROWS, 128, C_ROWS);
    dim3 gP(C_ROWS/128, 1);
    k_packB<<<(128*128+255)/256, 256>>>(wq, pbp, 128, 128);
    hgemm<0><<<gP, 256>>>(pap, pbp, pq, nullptr, C_ROWS, 128, 384);
    k_packB<<<(128*128+255)/256, 256>>>(wk, pbp, 128, 128);
    hgemm<0><<<gP, 256>>>(pap, pbp, pkk, nullptr, C_ROWS, 128, 384);
    k_packB<<<(128*128+255)/256, 256>>>(wv, pbp, 128, 128);
    hgemm<0><<<gP, 256>>>(pap, pbp, pv, nullptr, C_ROWS, 128, 384);

    k_softmax_d<<<C_ROWS/8, 256>>>(pq);
    k_softmax_L<<<C_BN, 128>>>(pkk);
    k_attn<<<C_BN, 256, SM_ATTN>>>();

    // enc += att0 @ wo^T
    k_packA<<<APACK_G, 256>>>(patt0, pap, C_ROWS, 128, C_ROWS);
    k_packB<<<(128*128+255)/256, 256>>>(wo, pbp, 128, 128);
    hgemm<3><<<gP, 256>>>(pap, pbp, penc, nullptr, C_ROWS, 128, 384);

    // FF block
    k_ln<<<C_ROWS/8, 256>>>(penc, ln2_g, ln2_b, ph);
    k_packA<<<APACK_G, 256>>>(ph, pap, C_ROWS, 128, C_ROWS);
    k_packB<<<(512*128+255)/256, 256>>>(ff_w1, pbp, 512, 128);
    hgemm<1><<<dim3(C_ROWS/128, 4), 256>>>(pap, pbp, pff, ff_b1, C_ROWS, 512, 384);
    k_packA<<<FFPACK_G, 256>>>(pff, pffp, C_ROWS, 512, C_ROWS);
    k_packB<<<(128*512+255)/256, 256>>>(ff_w2, pbp, 128, 512);
    hgemm<2><<<gP, 256>>>(pffp, pbp, penc, ff_b2, C_ROWS, 128, 1536);

    // spatial: agg = adj @ nf  (split-K3; agg -> g_ff, B2 -> g_b2 after FF2 done)
    k_bt<<<dim3(KPAD/32, C_ND/32, C_BL), 256>>>(pb2);
    hgemm<0><<<dim3(MPAD/128, NCOL/128), 256>>>(pa2, pb2, pagg, nullptr, C_NN, NCOL, KP);

    // pe2 = adj @ pe (small, fp32); pw = pe2 @ wpool (HMMA)
    sgemm_nn<<<dim3(24, 1), 256>>>(adj, ppe, ppe2, C_NN, 128, C_NN);
    k_packA<<<(int)(((size_t)MPAD*128 + 255)/256), 256>>>(ppe2, pap, C_NN, 128, MPAD);
    k_packBt<<<(16384*128+255)/256, 256>>>(wpool, pbp, 16384, 128);
    hgemm<0><<<dim3(MPAD/128, 128), 256>>>(pap, pbp, ppw, nullptr, C_NN, 16384, 384);

    k_group<<<C_NN, 256, SM_GRP>>>();
    k_gnred<<<C_BL*4, 256>>>();
    k_final<<<C_BN, 128>>>(gn_g, gn_b, p2_w, p2_b, p1_w, p1_b, out);
}

// round 10
// speedup vs baseline: 2.2414x; 1.4237x over previous
#include <cuda_runtime.h>
#include <cuda_bf16.h>
#include <math.h>
#include <stdint.h>

#define C_NB 2
#define C_NL 48
#define C_NN 3000
#define C_ND 128
#define C_NLOUT 24
#define C_BN (C_NB*C_NN)
#define C_ROWS (C_BN*C_NL)
#define C_BL (C_NB*C_NL)
#define KPAD 3008
#define MPAD 3072
#define NCOL (C_BL*C_ND)   // 12288

// ---------------- device-global scratch (aliased) ----------------
// g_agg aliases g_ff ; g_res aliases g_q ; FF2-packed input aliases g_b2
__device__ float g_mean[C_BN];
__device__ float g_enc [C_ROWS*C_ND];
__device__ float g_q   [C_ROWS*C_ND];          // also: g_res
__device__ float g_kk  [C_ROWS*C_ND];
__device__ float g_v   [C_ROWS*C_ND];
__device__ float g_ff  [C_ROWS*512];           // also: g_agg
__device__ float g_pe  [C_NN*C_ND];
__device__ float g_pe2 [C_NN*C_ND];
__device__ float g_pw  [(size_t)C_NN*C_ND*C_ND];
__device__ float g_gmu [C_BL*4];
__device__ float g_grs [C_BL*4];
__device__ __nv_bfloat16 g_a2 [(size_t)MPAD*KPAD];     // fp16 bits (adj*1024)
__device__ __nv_bfloat16 g_b2 [(size_t)C_ROWS*1536];   // fp16 nf^T  OR  FF2 packed input
__device__ __nv_bfloat16 g_ap [(size_t)C_ROWS*384];    // packed activations
__device__ __nv_bfloat16 g_bp [(size_t)16384*384];     // packed weights

__device__ __forceinline__ float geluf(float x){
    return 0.5f*x*(1.0f+erff(x*0.70710678118654752f));
}
__device__ __forceinline__ uint32_t smem_u32(const void* p){
    uint32_t a;
    asm("{ .reg .u64 t; cvta.to.shared.u64 t, %1; cvt.u32.u64 %0, t; }" : "=r"(a) : "l"(p));
    return a;
}
__device__ __forceinline__ void split_bf16(float v, __nv_bfloat16& h, __nv_bfloat16& lo){
    h = __float2bfloat16(v);
    lo = __float2bfloat16(v - __bfloat162float(h));
}
#define CP_ASYNC16(dst, src) asm volatile("cp.async.cg.shared.global [%0], [%1], 16;" :: "r"(dst), "l"(src))
#define CP_COMMIT() asm volatile("cp.async.commit_group;" ::: "memory")
#define CP_WAIT(n)  asm volatile("cp.async.wait_group %0;" :: "n"(n) : "memory")
#define LDSM4(r0,r1,r2,r3,addr) \
    asm volatile("ldmatrix.sync.aligned.m8n8.x4.shared.b16 {%0,%1,%2,%3}, [%4];" \
        : "=r"(r0),"=r"(r1),"=r"(r2),"=r"(r3) : "r"(addr))
#define MMA_BF16(d, a, b) asm volatile( \
    "mma.sync.aligned.m16n8k16.row.col.f32.bf16.bf16.f32 " \
    "{%0,%1,%2,%3}, {%4,%5,%6,%7}, {%8,%9}, {%0,%1,%2,%3};" \
    : "+f"((d)[0]),"+f"((d)[1]),"+f"((d)[2]),"+f"((d)[3]) \
    : "r"((a)[0]),"r"((a)[1]),"r"((a)[2]),"r"((a)[3]), "r"((b)[0]),"r"((b)[1]))
#define MMA_F16(d, a, b) asm volatile( \
    "mma.sync.aligned.m16n8k16.row.col.f32.f16.f16.f32 " \
    "{%0,%1,%2,%3}, {%4,%5,%6,%7}, {%8,%9}, {%0,%1,%2,%3};" \
    : "+f"((d)[0]),"+f"((d)[1]),"+f"((d)[2]),"+f"((d)[3]) \
    : "r"((a)[0]),"r"((a)[1]),"r"((a)[2]),"r"((a)[3]), "r"((b)[0]),"r"((b)[1]))

// ---------------- K1: mean + circular conv1d embedding ----------------
__global__ __launch_bounds__(128) void k_embed(const float* __restrict__ x_enc,
                                               const float* __restrict__ conv_w)
{
    int bn = blockIdx.x, b = bn / C_NN, n = bn % C_NN, t = threadIdx.x;
    __shared__ float red[128];
    __shared__ float xs[C_NL+2];
    float v = 0.f;
    if (t < C_NL) v = x_enc[(size_t)(b*C_NL + t)*C_NN + n];
    red[t] = v; __syncthreads();
    #pragma unroll
    for (int s = 64; s > 0; s >>= 1) { if (t < s) red[t] += red[t+s]; __syncthreads(); }
    float mean = red[0] * (1.f/C_NL);
    if (t == 0) g_mean[bn] = mean;
    if (t < C_NL) xs[t+1] = v - mean;
    __syncthreads();
    if (t == 0) { xs[0] = xs[C_NL]; xs[C_NL+1] = xs[1]; }
    __syncthreads();
    float w0 = conv_w[t*3], w1 = conv_w[t*3+1], w2 = conv_w[t*3+2];
    float* out = g_enc + (size_t)bn*C_NL*C_ND;
    #pragma unroll 4
    for (int l = 0; l < C_NL; l++)
        out[l*C_ND + t] = w0*xs[l] + w1*xs[l+1] + w2*xs[l+2];
}

// ---------------- pe projection ----------------
__global__ __launch_bounds__(256) void k_pe(const float* __restrict__ pe_raw,
    const float* __restrict__ pos_w, const float* __restrict__ pos_b)
{
    int idx = blockIdx.x*256 + threadIdx.x;
    if (idx >= C_NN*C_ND) return;
    int n = idx >> 7, d = idx & 127;
    g_pe[idx] = pe_raw[n]*pos_w[d*3] + pe_raw[C_NN+n]*pos_w[d*3+1]
              + pe_raw[2*C_NN+n]*pos_w[d*3+2] + pos_b[d];
}

// ---------------- LayerNorm -> packed bf16 [h|lo|h] directly ----------------
__global__ __launch_bounds__(256) void k_ln_pack(const float* __restrict__ in,
    const float* __restrict__ ga, const float* __restrict__ be,
    __nv_bfloat16* __restrict__ outp)
{
    int row = blockIdx.x*8 + (threadIdx.x>>5), lane = threadIdx.x & 31;
    float4 x = *(const float4*)(in + (size_t)row*C_ND + lane*4);
    float s = x.x+x.y+x.z+x.w;
    #pragma unroll
    for (int o=16;o;o>>=1) s += __shfl_xor_sync(~0u, s, o);
    float mean = s*(1.f/128.f);
    float dx=x.x-mean, dy=x.y-mean, dz=x.z-mean, dw=x.w-mean;
    float sq = dx*dx+dy*dy+dz*dz+dw*dw;
    #pragma unroll
    for (int o=16;o;o>>=1) sq += __shfl_xor_sync(~0u, sq, o);
    float rstd = rsqrtf(sq*(1.f/128.f) + 1e-5f);
    float4 g = *(const float4*)(ga + lane*4), bb = *(const float4*)(be + lane*4);
    float vv[4] = { dx*rstd*g.x+bb.x, dy*rstd*g.y+bb.y, dz*rstd*g.z+bb.z, dw*rstd*g.w+bb.w };
    __nv_bfloat16 h[4], lo[4];
    #pragma unroll
    for (int i=0;i<4;i++) split_bf16(vv[i], h[i], lo[i]);
    __nv_bfloat16* p = outp + (size_t)row*384 + lane*4;
    *(__nv_bfloat162*)(p)       = __nv_bfloat162{h[0],h[1]};
    *(__nv_bfloat162*)(p+2)     = __nv_bfloat162{h[2],h[3]};
    *(__nv_bfloat162*)(p+128)   = __nv_bfloat162{lo[0],lo[1]};
    *(__nv_bfloat162*)(p+130)   = __nv_bfloat162{lo[2],lo[3]};
    *(__nv_bfloat162*)(p+256)   = __nv_bfloat162{h[0],h[1]};
    *(__nv_bfloat162*)(p+258)   = __nv_bfloat162{h[2],h[3]};
}

// ---------------- softmax over d ----------------
__global__ __launch_bounds__(256) void k_softmax_d(float* __restrict__ buf)
{
    int row = blockIdx.x*8 + (threadIdx.x>>5), lane = threadIdx.x & 31;
    float* p = buf + (size_t)row*C_ND + lane*4;
    float4 x = *(const float4*)p;
    float m = fmaxf(fmaxf(x.x,x.y), fmaxf(x.z,x.w));
    #pragma unroll
    for (int o=16;o;o>>=1) m = fmaxf(m, __shfl_xor_sync(~0u, m, o));
    float4 e = make_float4(expf(x.x-m), expf(x.y-m), expf(x.z-m), expf(x.w-m));
    float s = e.x+e.y+e.z+e.w;
    #pragma unroll
    for (int o=16;o;o>>=1) s += __shfl_xor_sync(~0u, s, o);
    float sc = 0.08838834764831845f / s;
    e.x*=sc; e.y*=sc; e.z*=sc; e.w*=sc;
    *(float4*)p = e;
}

// ---------------- softmax over L ----------------
__global__ __launch_bounds__(128) void k_softmax_L(float* __restrict__ buf)
{
    int bn = blockIdx.x, d = threadIdx.x;
    float* p = buf + (size_t)bn*C_NL*C_ND + d;
    float v[C_NL], m = -1e30f;
    #pragma unroll
    for (int l=0;l<C_NL;l++){ v[l]=p[l*C_ND]; m=fmaxf(m,v[l]); }
    float s = 0.f;
    #pragma unroll
    for (int l=0;l<C_NL;l++){ v[l]=expf(v[l]-m); s+=v[l]; }
    float inv = 1.f/s;
    #pragma unroll
    for (int l=0;l<C_NL;l++) p[l*C_ND] = v[l]*inv;
}

// ---------------- tiled fp32 SGEMM (pe2 only) ----------------
#define TBK 16
#define SP 132
__global__ __launch_bounds__(256) void sgemm_nn(
    const float* __restrict__ A, const float* __restrict__ Bm,
    float* __restrict__ C, int M, int N, int K)
{
    __shared__ float As[TBK*SP];
    __shared__ float Bs[TBK*SP];
    const int tid = threadIdx.x, ty = tid>>4, tx = tid&15;
    const int rowBase = blockIdx.x*128, colBase = blockIdx.y*128;
    float acc[8][8];
    #pragma unroll
    for (int i=0;i<8;i++)
        #pragma unroll
        for (int j=0;j<8;j++) acc[i][j]=0.f;
    const int ar = tid>>2, ac = (tid&3)<<2;
    const int numT = (K+TBK-1)/TBK;
    for (int kt=0; kt<numT; kt++){
        const int k0 = kt*TBK;
        #pragma unroll
        for (int hh=0; hh<2; hh++){
            int row = rowBase + ar + hh*64, kg = k0 + ac;
            float4 av = make_float4(0,0,0,0);
            if (row < M){
                const float* ap = A + (size_t)row*K + kg;
                if (kg+3 < K) av = *(const float4*)ap;
                else { if(kg<K)av.x=ap[0]; if(kg+1<K)av.y=ap[1]; if(kg+2<K)av.z=ap[2]; }
            }
            As[(ac+0)*SP+ar+hh*64]=av.x; As[(ac+1)*SP+ar+hh*64]=av.y;
            As[(ac+2)*SP+ar+hh*64]=av.z; As[(ac+3)*SP+ar+hh*64]=av.w;
        }
        #pragma unroll
        for (int hh=0; hh<2; hh++){
            int kr = (tid>>5) + hh*8, c4 = (tid&31)<<2, kg = k0+kr;
            float4 bv = make_float4(0,0,0,0);
            if (kg < K) bv = *(const float4*)(Bm + (size_t)kg*N + colBase + c4);
            *(float4*)&Bs[kr*SP + c4] = bv;
        }
        __syncthreads();
        #pragma unroll
        for (int kk=0; kk<TBK; kk++){
            float4 a0 = *(const float4*)&As[kk*SP + ty*8];
            float4 a1 = *(const float4*)&As[kk*SP + ty*8 + 4];
            float4 b0 = *(const float4*)&Bs[kk*SP + tx*8];
            float4 b1 = *(const float4*)&Bs[kk*SP + tx*8 + 4];
            float av[8]={a0.x,a0.y,a0.z,a0.w,a1.x,a1.y,a1.z,a1.w};
            float bv[8]={b0.x,b0.y,b0.z,b0.w,b1.x,b1.y,b1.z,b1.w};
            #pragma unroll
            for (int i=0;i<8;i++)
                #pragma unroll
                for (int j=0;j<8;j++) acc[i][j] = fmaf(av[i], bv[j], acc[i][j]);
        }
        __syncthreads();
    }
    #pragma unroll
    for (int i=0;i<8;i++){
        int row = rowBase + ty*8 + i;
        if (row >= M) continue;
        float* cp = C + (size_t)row*N + colBase + tx*8;
        #pragma unroll
        for (int jj=0; jj<2; jj++)
            *(float4*)(cp+jj*4) = make_float4(acc[i][jj*4],acc[i][jj*4+1],acc[i][jj*4+2],acc[i][jj*4+3]);
    }
}

// ---------------- fused linear-attention core per bn (writes packed att0) ----
#define SM_ATTN ((2*48*132 + 128*132)*4)
__global__ __launch_bounds__(256) void k_attn()
{
    extern __shared__ float sm[];
    float* s_k = sm;
    float* s_v = sm + 48*132;
    float* s_c = sm + 2*48*132;
    const int bn = blockIdx.x, tid = threadIdx.x;
    const float* kb = g_kk + (size_t)bn*C_NL*C_ND;
    const float* vb = g_v  + (size_t)bn*C_NL*C_ND;
    for (int i = tid; i < (C_NL*C_ND)/4; i += 256){
        int e = i<<2, r = e>>7, c = e&127;
        *(float4*)&s_k[r*132+c] = *(const float4*)(kb+e);
        *(float4*)&s_v[r*132+c] = *(const float4*)(vb+e);
    }
    __syncthreads();
    const int ty = tid>>4, tx = tid&15;
    float acc[8][8];
    #pragma unroll
    for (int i=0;i<8;i++)
        #pragma unroll
        for (int j=0;j<8;j++) acc[i][j]=0.f;
    #pragma unroll 4
    for (int l=0;l<C_NL;l++){
        float4 a0 = *(const float4*)&s_k[l*132+ty*8];
        float4 a1 = *(const float4*)&s_k[l*132+ty*8+4];
        float4 b0 = *(const float4*)&s_v[l*132+tx*8];
        float4 b1 = *(const float4*)&s_v[l*132+tx*8+4];
        float av[8]={a0.x,a0.y,a0.z,a0.w,a1.x,a1.y,a1.z,a1.w};
        float bv[8]={b0.x,b0.y,b0.z,b0.w,b1.x,b1.y,b1.z,b1.w};
        #pragma unroll
        for (int i=0;i<8;i++)
            #pragma unroll
            for (int j=0;j<8;j++) acc[i][j] = fmaf(av[i], bv[j], acc[i][j]);
    }
    __syncthreads();
    #pragma unroll
    for (int i=0;i<8;i++)
        #pragma unroll
        for (int j=0;j<8;j++) s_c[(ty*8+i)*132 + tx*8+j] = acc[i][j];
    const float* qb = g_q + (size_t)bn*C_NL*C_ND;
    for (int i = tid; i < (C_NL*C_ND)/4; i += 256){
        int e = i<<2, r = e>>7, c = e&127;
        *(float4*)&s_k[r*132+c] = *(const float4*)(qb+e);
    }
    __syncthreads();
    const int lane = tid&31, warp = tid>>5;
    __nv_bfloat16* ob = g_ap + (size_t)bn*C_NL*384;
    for (int l = warp; l < C_NL; l += 8){
        float a4[4] = {0,0,0,0};
        #pragma unroll 4
        for (int d=0; d<C_ND; d+=4){
            float4 q4 = *(const float4*)&s_k[l*132+d];
            float4 c0 = *(const float4*)&s_c[(d+0)*132 + lane*4];
            float4 c1 = *(const float4*)&s_c[(d+1)*132 + lane*4];
            float4 c2 = *(const float4*)&s_c[(d+2)*132 + lane*4];
            float4 c3 = *(const float4*)&s_c[(d+3)*132 + lane*4];
            a4[0] += q4.x*c0.x + q4.y*c1.x + q4.z*c2.x + q4.w*c3.x;
            a4[1] += q4.x*c0.y + q4.y*c1.y + q4.z*c2.y + q4.w*c3.y;
            a4[2] += q4.x*c0.z + q4.y*c1.z + q4.z*c2.z + q4.w*c3.z;
            a4[3] += q4.x*c0.w + q4.y*c1.w + q4.z*c2.w + q4.w*c3.w;
        }
        __nv_bfloat16 h[4], lo[4];
        #pragma unroll
        for (int i=0;i<4;i++) split_bf16(a4[i], h[i], lo[i]);
        __nv_bfloat16* p = ob + l*384 + lane*4;
        *(__nv_bfloat162*)(p)     = __nv_bfloat162{h[0],h[1]};
        *(__nv_bfloat162*)(p+2)   = __nv_bfloat162{h[2],h[3]};
        *(__nv_bfloat162*)(p+128) = __nv_bfloat162{lo[0],lo[1]};
        *(__nv_bfloat162*)(p+130) = __nv_bfloat162{lo[2],lo[3]};
        *(__nv_bfloat162*)(p+256) = __nv_bfloat162{h[0],h[1]};
        *(__nv_bfloat162*)(p+258) = __nv_bfloat162{h[2],h[3]};
    }
}

// ---------------- adj -> fp16 (scaled by 1024), padded [MPAD][KPAD] ---------
__global__ __launch_bounds__(256) void k_split_adj_h(const float* __restrict__ adj)
{
    size_t idx = (size_t)blockIdx.x*256 + threadIdx.x;
    if (idx >= (size_t)MPAD*KPAD) return;
    int m = (int)(idx / KPAD), k = (int)(idx % KPAD);
    float v = (m < C_NN && k < C_NN) ? adj[(size_t)m*C_NN + k] * 1024.f : 0.f;
    ((__half*)g_a2)[idx] = __float2half(v);
}

// -------- build nf^T fp16: row c=(bl*128+d), col k=node --------------------
__global__ __launch_bounds__(256) void k_bt_h(__nv_bfloat16* __restrict__ B2)
{
    __shared__ float sm[32][33];
    int n0 = blockIdx.x*32, d0 = blockIdx.y*32, bl = blockIdx.z;
    int b = bl / C_NL, l = bl % C_NL;
    int tx = threadIdx.x & 31, ty = threadIdx.x >> 5;
    #pragma unroll
    for (int s=0;s<4;s++){
        int n = n0 + ty + s*8;
        float v = 0.f;
        if (n < C_NN) v = g_enc[((size_t)(b*C_NN + n)*C_NL + l)*C_ND + d0 + tx];
        sm[ty+s*8][tx] = v;
    }
    __syncthreads();
    #pragma unroll
    for (int s=0;s<4;s++){
        int dl = ty + s*8;
        float v = sm[tx][dl];
        ((__half*)B2)[(size_t)(bl*C_ND + d0 + dl)*KPAD + n0 + tx] = __float2half(v);
    }
}

// ---------------- pack activations A[M][K] -> [Ah|Al|Ah] --------------------
__global__ __launch_bounds__(256) void k_packA(const float* __restrict__ A,
    __nv_bfloat16* __restrict__ Ap, int M, int K, int Mpad)
{
    size_t idx = (size_t)blockIdx.x*256 + threadIdx.x;
    if (idx >= (size_t)Mpad*K) return;
    int row = (int)(idx / K), k = (int)(idx % K);
    float v = (row < M) ? A[(size_t)row*K + k] : 0.f;
    __nv_bfloat16 h, lo; split_bf16(v, h, lo);
    __nv_bfloat16* p = Ap + (size_t)row*3*K + k;
    p[0] = h; p[K] = lo; p[2*K] = h;
}

// ---------------- pack weights B[N][K] -> [Bh|Bh|Bl] ------------------------
__global__ __launch_bounds__(256) void k_packB(const float* __restrict__ B,
    __nv_bfloat16* __restrict__ Bp, int N, int K)
{
    int idx = blockIdx.x*256 + threadIdx.x;
    if (idx >= N*K) return;
    int n = idx / K, k = idx % K;
    float v = B[(size_t)n*K + k];
    __nv_bfloat16 h, lo; split_bf16(v, h, lo);
    __nv_bfloat16* p = Bp + (size_t)n*3*K + k;
    p[0] = h; p[K] = h; p[2*K] = lo;
}

// --------- pack transposed weights W[K][N] -> [Bh|Bh|Bl] --------------------
__global__ __launch_bounds__(256) void k_packBt(const float* __restrict__ W,
    __nv_bfloat16* __restrict__ Bp, int N, int K)
{
    int idx = blockIdx.x*256 + threadIdx.x;
    if (idx >= N*K) return;
    int n = idx / K, k = idx % K;
    float v = W[(size_t)k*N + n];
    __nv_bfloat16 h, lo; split_bf16(v, h, lo);
    __nv_bfloat16* p = Bp + (size_t)n*3*K + k;
    p[0] = h; p[K] = h; p[2*K] = lo;
}

// ---------------- generic HMMA GEMM: C[M][N] (+)= A @ B^T -------------------
// HALF: 0=bf16 inputs, 1=fp16 inputs.
// EPI: 0 store | 2 C += x+bias | 3 C += x | 4 gelu(x+bias)->packed bf16 Cp | 5 store x*oscale
template<int EPI, int HALF>
__global__ __launch_bounds__(256) void hgemm(
    const __nv_bfloat16* __restrict__ A, const __nv_bfloat16* __restrict__ Bm,
    float* __restrict__ C, __nv_bfloat16* __restrict__ Cp,
    const float* __restrict__ bias,
    int Mreal, int N, int K, float oscale)
{
    __shared__ __nv_bfloat16 As[2][128*40];
    __shared__ __nv_bfloat16 Bs[2][128*40];
    const int tid = threadIdx.x;
    const int mBase = blockIdx.x*128, cBase = blockIdx.y*128;
    const __nv_bfloat16* pA = A + (size_t)mBase*K;
    const __nv_bfloat16* pB = Bm + (size_t)cBase*K;
    const int warp = tid>>5, lane = tid&31;
    const int wm = warp&3, wn = warp>>2;
    float acc[2][8][4];
    #pragma unroll
    for (int i=0;i<2;i++)
        #pragma unroll
        for (int j=0;j<8;j++)
            #pragma unroll
            for (int q=0;q<4;q++) acc[i][j][q] = 0.f;

    #define PREFETCH(ck, buf) do { \
        int _k0 = (ck)*32; \
        _Pragma("unroll") \
        for (int _t=0; _t<4; _t++){ \
            int _j = _t*256 + tid; \
            int _jj = _j & 511; \
            int _r = _jj>>2, _seg = _jj&3; \
            const __nv_bfloat16* _src = ((_j < 512) ? pA : pB) + (size_t)_r*K + _k0 + _seg*8; \
            uint32_t _dst = smem_u32(((_j < 512) ? &As[buf][0] : &Bs[buf][0]) + _r*40 + _seg*8); \
            CP_ASYNC16(_dst, _src); \
        } \
        CP_COMMIT(); \
    } while(0)

    const int nck = K >> 5;
    PREFETCH(0, 0);
    for (int ck = 0; ck < nck; ck++){
        if (ck + 1 < nck){ PREFETCH(ck+1, (ck+1)&1); CP_WAIT(1); }
        else             { CP_WAIT(0); }
        __syncthreads();
        const __nv_bfloat16* as = &As[ck&1][0];
        const __nv_bfloat16* bs = &Bs[ck&1][0];
        #pragma unroll
        for (int ks=0; ks<2; ks++){
            const int kc = ks*16;
            uint32_t a[2][4], bfr[8][2];
            #pragma unroll
            for (int mt=0; mt<2; mt++){
                int row = wm*32 + mt*16 + (lane&7) + ((lane>>3)&1)*8;
                int col = kc + (lane>>4)*8;
                uint32_t ad = smem_u32(as + row*40 + col);
                LDSM4(a[mt][0], a[mt][1], a[mt][2], a[mt][3], ad);
            }
            #pragma unroll
            for (int p=0; p<4; p++){
                int row = wn*64 + p*16 + (lane>>4)*8 + (lane&7);
                int col = kc + ((lane>>3)&1)*8;
                uint32_t bd = smem_u32(bs + row*40 + col);
                uint32_t r0,r1,r2,r3;
                LDSM4(r0,r1,r2,r3, bd);
                bfr[p*2][0]=r0; bfr[p*2][1]=r1; bfr[p*2+1][0]=r2; bfr[p*2+1][1]=r3;
            }
            #pragma unroll
            for (int mt=0; mt<2; mt++)
                #pragma unroll
                for (int nt=0; nt<8; nt++){
                    if (HALF) { MMA_F16(acc[mt][nt], a[mt], bfr[nt]); }
                    else      { MMA_BF16(acc[mt][nt], a[mt], bfr[nt]); }
                }
        }
        __syncthreads();
    }
    #undef PREFETCH

    const int g = lane>>2, tg = lane&3;
    #pragma unroll
    for (int mt=0; mt<2; mt++){
        int rbase = mBase + wm*32 + mt*16 + g;
        #pragma unroll
        for (int half=0; half<2; half++){
            int r = rbase + half*8;
            if (r >= Mreal) continue;
            #pragma unroll
            for (int nt=0; nt<8; nt++){
                int c0 = cBase + wn*64 + nt*8 + tg*2;
                float v0 = acc[mt][nt][half*2], v1 = acc[mt][nt][half*2+1];
                if (EPI == 4){
                    float g0 = geluf(v0 + bias[c0]), g1 = geluf(v1 + bias[c0+1]);
                    __nv_bfloat16 h0,l0,h1,l1;
                    split_bf16(g0,h0,l0); split_bf16(g1,h1,l1);
                    __nv_bfloat16* pp = Cp + (size_t)r*3*N + c0;
                    *(__nv_bfloat162*)(pp)       = __nv_bfloat162{h0,h1};
                    *(__nv_bfloat162*)(pp + N)   = __nv_bfloat162{l0,l1};
                    *(__nv_bfloat162*)(pp + 2*N) = __nv_bfloat162{h0,h1};
                } else {
                    float* cp = &C[(size_t)r*N + c0];
                    if (EPI == 0){
                        *(float2*)cp = make_float2(v0, v1);
                    } else if (EPI == 5){
                        *(float2*)cp = make_float2(v0*oscale, v1*oscale);
                    } else if (EPI == 2){
                        float2 c = *(float2*)cp;
                        *(float2*)cp = make_float2(c.x + v0 + bias[c0], c.y + v1 + bias[c0+1]);
                    } else {
                        float2 c = *(float2*)cp;
                        *(float2*)cp = make_float2(c.x + v0, c.y + v1);
                    }
                }
            }
        }
    }
}

// ---------------- grouped per-node GEMM (agg=g_ff, res=g_q) ----------------
#define SM_GRP ((128*132 + 96*128)*4)
__global__ __launch_bounds__(256) void k_group()
{
    extern __shared__ float sm[];
    float* s_w = sm;
    float* s_a = sm + 128*132;
    const int n = blockIdx.x, tid = threadIdx.x;
    const float* wb = g_pw + (size_t)n*C_ND*C_ND;
    const float* ab = g_ff + (size_t)n*C_BL*C_ND;
    for (int i = tid; i < (C_ND*C_ND)/4; i += 256){
        int e = i<<2, r = e>>7, c = e&127;
        *(float4*)&s_w[r*132+c] = *(const float4*)(wb+e);
    }
    for (int i = tid; i < (C_BL*C_ND)/4; i += 256)
        ((float4*)s_a)[i] = ((const float4*)ab)[i];
    __syncthreads();
    const int ty = tid>>4, tx = tid&15;
    float acc[6][8];
    #pragma unroll
    for (int i=0;i<6;i++)
        #pragma unroll
        for (int j=0;j<8;j++) acc[i][j]=0.f;
    #pragma unroll 4
    for (int k=0;k<C_ND;k++){
        float4 b0 = *(const float4*)&s_w[k*132 + tx*8];
        float4 b1 = *(const float4*)&s_w[k*132 + tx*8+4];
        float bv[8]={b0.x,b0.y,b0.z,b0.w,b1.x,b1.y,b1.z,b1.w};
        #pragma unroll
        for (int i=0;i<6;i++){
            float a = s_a[(ty*6+i)*C_ND + k];
            #pragma unroll
            for (int j=0;j<8;j++) acc[i][j] = fmaf(a, bv[j], acc[i][j]);
        }
    }
    float* ob = g_q + (size_t)n*C_BL*C_ND;
    #pragma unroll
    for (int i=0;i<6;i++){
        #pragma unroll
        for (int jj=0;jj<2;jj++){
            float4 vv = make_float4(acc[i][jj*4],acc[i][jj*4+1],acc[i][jj*4+2],acc[i][jj*4+3]);
            *(float4*)(ob + (ty*6+i)*C_ND + tx*8 + jj*4) = vv;
        }
    }
}

// ---------------- GroupNorm stats (res = g_q) ----------------
__global__ __launch_bounds__(256) void k_gnred()
{
    int bl = blockIdx.x>>2, g = blockIdx.x&3;
    int base = bl*C_ND + g*32;
    float s = 0.f, ss = 0.f;
    for (int i = threadIdx.x; i < C_NN*32; i += 256){
        int n = i>>5, o = i&31;
        float v = g_q[(size_t)n*C_BL*C_ND + base + o];
        s += v; ss += v*v;
    }
    __shared__ float r1[256], r2[256];
    r1[threadIdx.x]=s; r2[threadIdx.x]=ss; __syncthreads();
    for (int st=128; st>0; st>>=1){
        if (threadIdx.x < st){ r1[threadIdx.x]+=r1[threadIdx.x+st]; r2[threadIdx.x]+=r2[threadIdx.x+st]; }
        __syncthreads();
    }
    if (threadIdx.x == 0){
        float mean = r1[0]/(C_NN*32.0f);
        float var = r2[0]/(C_NN*32.0f) - mean*mean;
        g_gmu[blockIdx.x] = mean;
        g_grs[blockIdx.x] = rsqrtf(var + 1e-5f);
    }
}

// ---------------- final fused (res = g_q) ----------------
__global__ __launch_bounds__(128) void k_final(
    const float* __restrict__ gn_g, const float* __restrict__ gn_b,
    const float* __restrict__ p2_w, const float* __restrict__ p2_b,
    const float* __restrict__ p1_w, const float* __restrict__ p1_b,
    float* __restrict__ out)
{
    int bn = blockIdx.x, b = bn / C_NN, n = bn % C_NN;
    int lane = threadIdx.x & 31, warp = threadIdx.x >> 5;
    __shared__ float s_s[C_NL];
    int d0 = lane*4, g = d0 >> 5;
    float4 gg = *(const float4*)(gn_g + d0);
    float4 gb = *(const float4*)(gn_b + d0);
    float4 pw = *(const float4*)(p2_w + d0);
    float p2b = p2_b[0];
    for (int l = warp; l < C_NL; l += 4){
        int bl = b*C_NL + l;
        float mu = g_gmu[bl*4 + g], rs = g_grs[bl*4 + g];
        float4 x = *(const float4*)(g_q + (size_t)n*C_BL*C_ND + bl*C_ND + d0);
        float dot = ((x.x-mu)*rs*gg.x+gb.x)*pw.x + ((x.y-mu)*rs*gg.y+gb.y)*pw.y
                  + ((x.z-mu)*rs*gg.z+gb.z)*pw.z + ((x.w-mu)*rs*gg.w+gb.w)*pw.w;
        #pragma unroll
        for (int o=16;o;o>>=1) dot += __shfl_xor_sync(~0u, dot, o);
        if (lane == 0){
            float sv = dot + p2b;
            s_s[l] = sv / (1.f + expf(-sv));
        }
    }
    __syncthreads();
    if (threadIdx.x < C_NLOUT){
        float acc = p1_b[threadIdx.x];
        #pragma unroll
        for (int l=0;l<C_NL;l++) acc = fmaf(p1_w[threadIdx.x*C_NL + l], s_s[l], acc);
        out[(size_t)b*C_NLOUT*C_NN + threadIdx.x*C_NN + n] = acc + g_mean[bn];
    }
}

// ---------------- driver ----------------
extern "C" void kernel_launch(void* const* d_in, const int* in_sizes, int n_in,
                              void* d_out, int out_size)
{
    const float* x_enc = (const float*)d_in[0];
    const float* adj   = (const float*)d_in[1];
    const float* pe_raw= (const float*)d_in[2];
    const float* conv_w= (const float*)d_in[3];
    const float* pos_w = (const float*)d_in[4];
    const float* pos_b = (const float*)d_in[5];
    const float* wq    = (const float*)d_in[6];
    const float* wk    = (const float*)d_in[7];
    const float* wv    = (const float*)d_in[8];
    const float* wo    = (const float*)d_in[9];
    const float* ln1_g = (const float*)d_in[10];
    const float* ln1_b = (const float*)d_in[11];
    const float* ff_w1 = (const float*)d_in[12];
    const float* ff_b1 = (const float*)d_in[13];
    const float* ff_w2 = (const float*)d_in[14];
    const float* ff_b2 = (const float*)d_in[15];
    const float* ln2_g = (const float*)d_in[16];
    const float* ln2_b = (const float*)d_in[17];
    const float* wpool = (const float*)d_in[18];
    const float* gn_g  = (const float*)d_in[19];
    const float* gn_b  = (const float*)d_in[20];
    const float* p2_w  = (const float*)d_in[21];
    const float* p2_b  = (const float*)d_in[22];
    const float* p1_w  = (const float*)d_in[23];
    const float* p1_b  = (const float*)d_in[24];
    float* out = (float*)d_out;

    cudaFuncSetAttribute(k_attn,  cudaFuncAttributeMaxDynamicSharedMemorySize, SM_ATTN);
    cudaFuncSetAttribute(k_group, cudaFuncAttributeMaxDynamicSharedMemorySize, SM_GRP);

    float *penc, *pq, *pkk, *pv, *pff, *ppe, *ppe2, *ppw;
    __nv_bfloat16 *pa2, *pb2, *pap, *pbp;
    cudaGetSymbolAddress((void**)&penc,  g_enc);
    cudaGetSymbolAddress((void**)&pq,    g_q);
    cudaGetSymbolAddress((void**)&pkk,   g_kk);
    cudaGetSymbolAddress((void**)&pv,    g_v);
    cudaGetSymbolAddress((void**)&pff,   g_ff);
    cudaGetSymbolAddress((void**)&ppe,   g_pe);
    cudaGetSymbolAddress((void**)&ppe2,  g_pe2);
    cudaGetSymbolAddress((void**)&ppw,   g_pw);
    cudaGetSymbolAddress((void**)&pa2,   g_a2);
    cudaGetSymbolAddress((void**)&pb2,   g_b2);
    cudaGetSymbolAddress((void**)&pap,   g_ap);
    cudaGetSymbolAddress((void**)&pbp,   g_bp);

    __nv_bfloat16* pffp = pb2;   // FF2 packed input aliases g_b2
    float* pagg = pff;           // spatial agg aliases g_ff

    k_embed<<<C_BN, 128>>>(x_enc, conv_w);
    k_pe<<<(C_NN*C_ND + 255)/256, 256>>>(pe_raw, pos_w, pos_b);
    k_split_adj_h<<<(int)(((size_t)MPAD*KPAD + 255)/256), 256>>>(adj);

    // LN1 -> packed; q/k/v projections (bf16 split-K3)
    k_ln_pack<<<C_ROWS/8, 256>>>(penc, ln1_g, ln1_b, pap);
    dim3 gP(C_ROWS/128, 1);
    k_packB<<<(128*128+255)/256, 256>>>(wq, pbp, 128, 128);
    hgemm<0,0><<<gP, 256>>>(pap, pbp, pq, nullptr, nullptr, C_ROWS, 128, 384, 1.f);
    k_packB<<<(128*128+255)/256, 256>>>(wk, pbp, 128, 128);
    hgemm<0,0><<<gP, 256>>>(pap, pbp, pkk, nullptr, nullptr, C_ROWS, 128, 384, 1.f);
    k_packB<<<(128*128+255)/256, 256>>>(wv, pbp, 128, 128);
    hgemm<0,0><<<gP, 256>>>(pap, pbp, pv, nullptr, nullptr, C_ROWS, 128, 384, 1.f);

    k_softmax_d<<<C_ROWS/8, 256>>>(pq);
    k_softmax_L<<<C_BN, 128>>>(pkk);
    k_attn<<<C_BN, 256, SM_ATTN>>>();       // writes packed att0 into g_ap

    // enc += att0 @ wo^T
    k_packB<<<(128*128+255)/256, 256>>>(wo, pbp, 128, 128);
    hgemm<3,0><<<gP, 256>>>(pap, pbp, penc, nullptr, nullptr, C_ROWS, 128, 384, 1.f);

    // FF block: LN2 -> packed; FF1 -> packed (EPI=4); FF2 accumulate
    k_ln_pack<<<C_ROWS/8, 256>>>(penc, ln2_g, ln2_b, pap);
    k_packB<<<(512*128+255)/256, 256>>>(ff_w1, pbp, 512, 128);
    hgemm<4,0><<<dim3(C_ROWS/128, 4), 256>>>(pap, pbp, nullptr, pffp, ff_b1, C_ROWS, 512, 384, 1.f);
    k_packB<<<(128*512+255)/256, 256>>>(ff_w2, pbp, 128, 512);
    hgemm<2,0><<<gP, 256>>>(pffp, pbp, penc, nullptr, ff_b2, C_ROWS, 128, 1536, 1.f);

    // spatial: agg = adj @ nf  — plain fp16, A scaled x1024, epilogue x(1/1024)
    k_bt_h<<<dim3(KPAD/32, C_ND/32, C_BL), 256>>>(pb2);
    hgemm<5,1><<<dim3(MPAD/128, NCOL/128), 256>>>(pa2, pb2, pagg, nullptr, nullptr,
                                                  C_NN, NCOL, KPAD, 1.f/1024.f);

    // pe2 = adj @ pe (fp32); pw = pe2 @ wpool (bf16 split-K3)
    sgemm_nn<<<dim3(24, 1), 256>>>(adj, ppe, ppe2, C_NN, 128, C_NN);
    k_packA<<<(int)(((size_t)MPAD*128 + 255)/256), 256>>>(ppe2, pap, C_NN, 128, MPAD);
    k_packBt<<<(16384*128+255)/256, 256>>>(wpool, pbp, 16384, 128);
    hgemm<0,0><<<dim3(MPAD/128, 128), 256>>>(pap, pbp, ppw, nullptr, nullptr, C_NN, 16384, 384, 1.f);

    k_group<<<C_NN, 256, SM_GRP>>>();
    k_gnred<<<C_BL*4, 256>>>();
    k_final<<<C_BN, 128>>>(gn_g, gn_b, p2_w, p2_b, p1_w, p1_b, out);
}

// round 11
// speedup vs baseline: 2.7069x; 1.2077x over previous
#include <cuda_runtime.h>
#include <cuda_bf16.h>
#include <cuda_fp16.h>
#include <math.h>
#include <stdint.h>

#define C_NB 2
#define C_NL 48
#define C_NN 3000
#define C_ND 128
#define C_NLOUT 24
#define C_BN (C_NB*C_NN)
#define C_ROWS (C_BN*C_NL)
#define C_BL (C_NB*C_NL)
#define KPAD 3008
#define MPAD 3072
#define NCOL (C_BL*C_ND)   // 12288

// ---------------- device-global scratch (aliased) ----------------
// g_agg aliases g_ff ; g_res aliases g_q ; FF2 fp16 input aliases g_b2
__device__ float g_mean[C_BN];
__device__ float g_enc [C_ROWS*C_ND];
__device__ float g_q   [C_ROWS*C_ND];          // also: g_res
__device__ float g_kk  [C_ROWS*C_ND];
__device__ float g_v   [C_ROWS*C_ND];
__device__ float g_ff  [C_ROWS*512];           // also: g_agg
__device__ float g_pe  [C_NN*C_ND];
__device__ float g_pe2 [C_NN*C_ND];
__device__ float g_pw  [(size_t)C_NN*C_ND*C_ND];
__device__ float g_gmu [C_BL*4];
__device__ float g_grs [C_BL*4];
__device__ __nv_bfloat16 g_a2 [(size_t)MPAD*KPAD];     // fp16 bits (adj*1024)
__device__ __nv_bfloat16 g_b2 [(size_t)C_ROWS*1536];   // fp16 nf^T  OR  fp16 FF mid
__device__ __nv_bfloat16 g_ap [(size_t)C_ROWS*384];    // fp16 activations / bf16 packed pe2
__device__ __nv_bfloat16 g_bp [(size_t)16384*384];     // packed weights

__device__ __forceinline__ float geluf(float x){
    return 0.5f*x*(1.0f+erff(x*0.70710678118654752f));
}
__device__ __forceinline__ uint32_t smem_u32(const void* p){
    uint32_t a;
    asm("{ .reg .u64 t; cvta.to.shared.u64 t, %1; cvt.u32.u64 %0, t; }" : "=r"(a) : "l"(p));
    return a;
}
__device__ __forceinline__ void split_bf16(float v, __nv_bfloat16& h, __nv_bfloat16& lo){
    h = __float2bfloat16(v);
    lo = __float2bfloat16(v - __bfloat162float(h));
}
#define CP_ASYNC16(dst, src) asm volatile("cp.async.cg.shared.global [%0], [%1], 16;" :: "r"(dst), "l"(src))
#define CP_COMMIT() asm volatile("cp.async.commit_group;" ::: "memory")
#define CP_WAIT(n)  asm volatile("cp.async.wait_group %0;" :: "n"(n) : "memory")
#define LDSM4(r0,r1,r2,r3,addr) \
    asm volatile("ldmatrix.sync.aligned.m8n8.x4.shared.b16 {%0,%1,%2,%3}, [%4];" \
        : "=r"(r0),"=r"(r1),"=r"(r2),"=r"(r3) : "r"(addr))
#define MMA_BF16(d, a, b) asm volatile( \
    "mma.sync.aligned.m16n8k16.row.col.f32.bf16.bf16.f32 " \
    "{%0,%1,%2,%3}, {%4,%5,%6,%7}, {%8,%9}, {%0,%1,%2,%3};" \
    : "+f"((d)[0]),"+f"((d)[1]),"+f"((d)[2]),"+f"((d)[3]) \
    : "r"((a)[0]),"r"((a)[1]),"r"((a)[2]),"r"((a)[3]), "r"((b)[0]),"r"((b)[1]))
#define MMA_F16(d, a, b) asm volatile( \
    "mma.sync.aligned.m16n8k16.row.col.f32.f16.f16.f32 " \
    "{%0,%1,%2,%3}, {%4,%5,%6,%7}, {%8,%9}, {%0,%1,%2,%3};" \
    : "+f"((d)[0]),"+f"((d)[1]),"+f"((d)[2]),"+f"((d)[3]) \
    : "r"((a)[0]),"r"((a)[1]),"r"((a)[2]),"r"((a)[3]), "r"((b)[0]),"r"((b)[1]))

// ---------------- K1: mean + circular conv1d embedding ----------------
__global__ __launch_bounds__(128) void k_embed(const float* __restrict__ x_enc,
                                               const float* __restrict__ conv_w)
{
    int bn = blockIdx.x, b = bn / C_NN, n = bn % C_NN, t = threadIdx.x;
    __shared__ float red[128];
    __shared__ float xs[C_NL+2];
    float v = 0.f;
    if (t < C_NL) v = x_enc[(size_t)(b*C_NL + t)*C_NN + n];
    red[t] = v; __syncthreads();
    #pragma unroll
    for (int s = 64; s > 0; s >>= 1) { if (t < s) red[t] += red[t+s]; __syncthreads(); }
    float mean = red[0] * (1.f/C_NL);
    if (t == 0) g_mean[bn] = mean;
    if (t < C_NL) xs[t+1] = v - mean;
    __syncthreads();
    if (t == 0) { xs[0] = xs[C_NL]; xs[C_NL+1] = xs[1]; }
    __syncthreads();
    float w0 = conv_w[t*3], w1 = conv_w[t*3+1], w2 = conv_w[t*3+2];
    float* out = g_enc + (size_t)bn*C_NL*C_ND;
    #pragma unroll 4
    for (int l = 0; l < C_NL; l++)
        out[l*C_ND + t] = w0*xs[l] + w1*xs[l+1] + w2*xs[l+2];
}

// ---------------- pe projection ----------------
__global__ __launch_bounds__(256) void k_pe(const float* __restrict__ pe_raw,
    const float* __restrict__ pos_w, const float* __restrict__ pos_b)
{
    int idx = blockIdx.x*256 + threadIdx.x;
    if (idx >= C_NN*C_ND) return;
    int n = idx >> 7, d = idx & 127;
    g_pe[idx] = pe_raw[n]*pos_w[d*3] + pe_raw[C_NN+n]*pos_w[d*3+1]
              + pe_raw[2*C_NN+n]*pos_w[d*3+2] + pos_b[d];
}

// ---------------- LayerNorm -> fp16 row [row][128] ----------------
__global__ __launch_bounds__(256) void k_ln_h(const float* __restrict__ in,
    const float* __restrict__ ga, const float* __restrict__ be,
    __half* __restrict__ outp)
{
    int row = blockIdx.x*8 + (threadIdx.x>>5), lane = threadIdx.x & 31;
    float4 x = *(const float4*)(in + (size_t)row*C_ND + lane*4);
    float s = x.x+x.y+x.z+x.w;
    #pragma unroll
    for (int o=16;o;o>>=1) s += __shfl_xor_sync(~0u, s, o);
    float mean = s*(1.f/128.f);
    float dx=x.x-mean, dy=x.y-mean, dz=x.z-mean, dw=x.w-mean;
    float sq = dx*dx+dy*dy+dz*dz+dw*dw;
    #pragma unroll
    for (int o=16;o;o>>=1) sq += __shfl_xor_sync(~0u, sq, o);
    float rstd = rsqrtf(sq*(1.f/128.f) + 1e-5f);
    float4 g = *(const float4*)(ga + lane*4), bb = *(const float4*)(be + lane*4);
    __half* p = outp + (size_t)row*C_ND + lane*4;
    *(__half2*)(p)   = __floats2half2_rn(dx*rstd*g.x+bb.x, dy*rstd*g.y+bb.y);
    *(__half2*)(p+2) = __floats2half2_rn(dz*rstd*g.z+bb.z, dw*rstd*g.w+bb.w);
}

// ---------------- softmax over d ----------------
__global__ __launch_bounds__(256) void k_softmax_d(float* __restrict__ buf)
{
    int row = blockIdx.x*8 + (threadIdx.x>>5), lane = threadIdx.x & 31;
    float* p = buf + (size_t)row*C_ND + lane*4;
    float4 x = *(const float4*)p;
    float m = fmaxf(fmaxf(x.x,x.y), fmaxf(x.z,x.w));
    #pragma unroll
    for (int o=16;o;o>>=1) m = fmaxf(m, __shfl_xor_sync(~0u, m, o));
    float4 e = make_float4(expf(x.x-m), expf(x.y-m), expf(x.z-m), expf(x.w-m));
    float s = e.x+e.y+e.z+e.w;
    #pragma unroll
    for (int o=16;o;o>>=1) s += __shfl_xor_sync(~0u, s, o);
    float sc = 0.08838834764831845f / s;
    e.x*=sc; e.y*=sc; e.z*=sc; e.w*=sc;
    *(float4*)p = e;
}

// ---------------- softmax over L ----------------
__global__ __launch_bounds__(128) void k_softmax_L(float* __restrict__ buf)
{
    int bn = blockIdx.x, d = threadIdx.x;
    float* p = buf + (size_t)bn*C_NL*C_ND + d;
    float v[C_NL], m = -1e30f;
    #pragma unroll
    for (int l=0;l<C_NL;l++){ v[l]=p[l*C_ND]; m=fmaxf(m,v[l]); }
    float s = 0.f;
    #pragma unroll
    for (int l=0;l<C_NL;l++){ v[l]=expf(v[l]-m); s+=v[l]; }
    float inv = 1.f/s;
    #pragma unroll
    for (int l=0;l<C_NL;l++) p[l*C_ND] = v[l]*inv;
}

// ---------------- tiled fp32 SGEMM (pe2 only) ----------------
#define TBK 16
#define SP 132
__global__ __launch_bounds__(256) void sgemm_nn(
    const float* __restrict__ A, const float* __restrict__ Bm,
    float* __restrict__ C, int M, int N, int K)
{
    __shared__ float As[TBK*SP];
    __shared__ float Bs[TBK*SP];
    const int tid = threadIdx.x, ty = tid>>4, tx = tid&15;
    const int rowBase = blockIdx.x*128, colBase = blockIdx.y*128;
    float acc[8][8];
    #pragma unroll
    for (int i=0;i<8;i++)
        #pragma unroll
        for (int j=0;j<8;j++) acc[i][j]=0.f;
    const int ar = tid>>2, ac = (tid&3)<<2;
    const int numT = (K+TBK-1)/TBK;
    for (int kt=0; kt<numT; kt++){
        const int k0 = kt*TBK;
        #pragma unroll
        for (int hh=0; hh<2; hh++){
            int row = rowBase + ar + hh*64, kg = k0 + ac;
            float4 av = make_float4(0,0,0,0);
            if (row < M){
                const float* ap = A + (size_t)row*K + kg;
                if (kg+3 < K) av = *(const float4*)ap;
                else { if(kg<K)av.x=ap[0]; if(kg+1<K)av.y=ap[1]; if(kg+2<K)av.z=ap[2]; }
            }
            As[(ac+0)*SP+ar+hh*64]=av.x; As[(ac+1)*SP+ar+hh*64]=av.y;
            As[(ac+2)*SP+ar+hh*64]=av.z; As[(ac+3)*SP+ar+hh*64]=av.w;
        }
        #pragma unroll
        for (int hh=0; hh<2; hh++){
            int kr = (tid>>5) + hh*8, c4 = (tid&31)<<2, kg = k0+kr;
            float4 bv = make_float4(0,0,0,0);
            if (kg < K) bv = *(const float4*)(Bm + (size_t)kg*N + colBase + c4);
            *(float4*)&Bs[kr*SP + c4] = bv;
        }
        __syncthreads();
        #pragma unroll
        for (int kk=0; kk<TBK; kk++){
            float4 a0 = *(const float4*)&As[kk*SP + ty*8];
            float4 a1 = *(const float4*)&As[kk*SP + ty*8 + 4];
            float4 b0 = *(const float4*)&Bs[kk*SP + tx*8];
            float4 b1 = *(const float4*)&Bs[kk*SP + tx*8 + 4];
            float av[8]={a0.x,a0.y,a0.z,a0.w,a1.x,a1.y,a1.z,a1.w};
            float bv[8]={b0.x,b0.y,b0.z,b0.w,b1.x,b1.y,b1.z,b1.w};
            #pragma unroll
            for (int i=0;i<8;i++)
                #pragma unroll
                for (int j=0;j<8;j++) acc[i][j] = fmaf(av[i], bv[j], acc[i][j]);
        }
        __syncthreads();
    }
    #pragma unroll
    for (int i=0;i<8;i++){
        int row = rowBase + ty*8 + i;
        if (row >= M) continue;
        float* cp = C + (size_t)row*N + colBase + tx*8;
        #pragma unroll
        for (int jj=0; jj<2; jj++)
            *(float4*)(cp+jj*4) = make_float4(acc[i][jj*4],acc[i][jj*4+1],acc[i][jj*4+2],acc[i][jj*4+3]);
    }
}

// -------- fused linear-attention core per bn (writes fp16 att0) --------
#define SM_ATTN ((2*48*132 + 128*132)*4)
__global__ __launch_bounds__(256) void k_attn()
{
    extern __shared__ float sm[];
    float* s_k = sm;
    float* s_v = sm + 48*132;
    float* s_c = sm + 2*48*132;
    const int bn = blockIdx.x, tid = threadIdx.x;
    const float* kb = g_kk + (size_t)bn*C_NL*C_ND;
    const float* vb = g_v  + (size_t)bn*C_NL*C_ND;
    for (int i = tid; i < (C_NL*C_ND)/4; i += 256){
        int e = i<<2, r = e>>7, c = e&127;
        *(float4*)&s_k[r*132+c] = *(const float4*)(kb+e);
        *(float4*)&s_v[r*132+c] = *(const float4*)(vb+e);
    }
    __syncthreads();
    const int ty = tid>>4, tx = tid&15;
    float acc[8][8];
    #pragma unroll
    for (int i=0;i<8;i++)
        #pragma unroll
        for (int j=0;j<8;j++) acc[i][j]=0.f;
    #pragma unroll 4
    for (int l=0;l<C_NL;l++){
        float4 a0 = *(const float4*)&s_k[l*132+ty*8];
        float4 a1 = *(const float4*)&s_k[l*132+ty*8+4];
        float4 b0 = *(const float4*)&s_v[l*132+tx*8];
        float4 b1 = *(const float4*)&s_v[l*132+tx*8+4];
        float av[8]={a0.x,a0.y,a0.z,a0.w,a1.x,a1.y,a1.z,a1.w};
        float bv[8]={b0.x,b0.y,b0.z,b0.w,b1.x,b1.y,b1.z,b1.w};
        #pragma unroll
        for (int i=0;i<8;i++)
            #pragma unroll
            for (int j=0;j<8;j++) acc[i][j] = fmaf(av[i], bv[j], acc[i][j]);
    }
    __syncthreads();
    #pragma unroll
    for (int i=0;i<8;i++)
        #pragma unroll
        for (int j=0;j<8;j++) s_c[(ty*8+i)*132 + tx*8+j] = acc[i][j];
    const float* qb = g_q + (size_t)bn*C_NL*C_ND;
    for (int i = tid; i < (C_NL*C_ND)/4; i += 256){
        int e = i<<2, r = e>>7, c = e&127;
        *(float4*)&s_k[r*132+c] = *(const float4*)(qb+e);
    }
    __syncthreads();
    const int lane = tid&31, warp = tid>>5;
    __half* ob = (__half*)g_ap + (size_t)bn*C_NL*C_ND;
    for (int l = warp; l < C_NL; l += 8){
        float a4[4] = {0,0,0,0};
        #pragma unroll 4
        for (int d=0; d<C_ND; d+=4){
            float4 q4 = *(const float4*)&s_k[l*132+d];
            float4 c0 = *(const float4*)&s_c[(d+0)*132 + lane*4];
            float4 c1 = *(const float4*)&s_c[(d+1)*132 + lane*4];
            float4 c2 = *(const float4*)&s_c[(d+2)*132 + lane*4];
            float4 c3 = *(const float4*)&s_c[(d+3)*132 + lane*4];
            a4[0] += q4.x*c0.x + q4.y*c1.x + q4.z*c2.x + q4.w*c3.x;
            a4[1] += q4.x*c0.y + q4.y*c1.y + q4.z*c2.y + q4.w*c3.y;
            a4[2] += q4.x*c0.z + q4.y*c1.z + q4.z*c2.z + q4.w*c3.z;
            a4[3] += q4.x*c0.w + q4.y*c1.w + q4.z*c2.w + q4.w*c3.w;
        }
        __half* p = ob + l*C_ND + lane*4;
        *(__half2*)(p)   = __floats2half2_rn(a4[0], a4[1]);
        *(__half2*)(p+2) = __floats2half2_rn(a4[2], a4[3]);
    }
}

// ---------------- adj -> fp16 (scaled by 1024), padded [MPAD][KPAD] ---------
__global__ __launch_bounds__(256) void k_split_adj_h(const float* __restrict__ adj)
{
    size_t idx = (size_t)blockIdx.x*256 + threadIdx.x;
    if (idx >= (size_t)MPAD*KPAD) return;
    int m = (int)(idx / KPAD), k = (int)(idx % KPAD);
    float v = (m < C_NN && k < C_NN) ? adj[(size_t)m*C_NN + k] * 1024.f : 0.f;
    ((__half*)g_a2)[idx] = __float2half(v);
}

// -------- build nf^T fp16: row c=(bl*128+d), col k=node --------------------
__global__ __launch_bounds__(256) void k_bt_h(__nv_bfloat16* __restrict__ B2)
{
    __shared__ float sm[32][33];
    int n0 = blockIdx.x*32, d0 = blockIdx.y*32, bl = blockIdx.z;
    int b = bl / C_NL, l = bl % C_NL;
    int tx = threadIdx.x & 31, ty = threadIdx.x >> 5;
    #pragma unroll
    for (int s=0;s<4;s++){
        int n = n0 + ty + s*8;
        float v = 0.f;
        if (n < C_NN) v = g_enc[((size_t)(b*C_NN + n)*C_NL + l)*C_ND + d0 + tx];
        sm[ty+s*8][tx] = v;
    }
    __syncthreads();
    #pragma unroll
    for (int s=0;s<4;s++){
        int dl = ty + s*8;
        float v = sm[tx][dl];
        ((__half*)B2)[(size_t)(bl*C_ND + d0 + dl)*KPAD + n0 + tx] = __float2half(v);
    }
}

// ---------------- pack activations A[M][K] -> [Ah|Al|Ah] bf16 ----------------
__global__ __launch_bounds__(256) void k_packA(const float* __restrict__ A,
    __nv_bfloat16* __restrict__ Ap, int M, int K, int Mpad)
{
    size_t idx = (size_t)blockIdx.x*256 + threadIdx.x;
    if (idx >= (size_t)Mpad*K) return;
    int row = (int)(idx / K), k = (int)(idx % K);
    float v = (row < M) ? A[(size_t)row*K + k] : 0.f;
    __nv_bfloat16 h, lo; split_bf16(v, h, lo);
    __nv_bfloat16* p = Ap + (size_t)row*3*K + k;
    p[0] = h; p[K] = lo; p[2*K] = h;
}

// --------- pack transposed weights W[K][N] -> [Bh|Bh|Bl] bf16 ----------------
__global__ __launch_bounds__(256) void k_packBt(const float* __restrict__ W,
    __nv_bfloat16* __restrict__ Bp, int N, int K)
{
    int idx = blockIdx.x*256 + threadIdx.x;
    if (idx >= N*K) return;
    int n = idx / K, k = idx % K;
    float v = W[(size_t)k*N + n];
    __nv_bfloat16 h, lo; split_bf16(v, h, lo);
    __nv_bfloat16* p = Bp + (size_t)n*3*K + k;
    p[0] = h; p[K] = h; p[2*K] = lo;
}

// ---------------- weight -> plain fp16 copy ----------------
__global__ __launch_bounds__(256) void k_packW_h(const float* __restrict__ W,
    __half* __restrict__ out, int nElem)
{
    int idx = blockIdx.x*256 + threadIdx.x;
    if (idx < nElem) out[idx] = __float2half(W[idx]);
}

// ---------------- generic HMMA GEMM: C[M][N] (+)= A @ B^T -------------------
// HALF: 0=bf16 inputs, 1=fp16 inputs.
// EPI: 0 store | 2 C += x+bias | 3 C += x | 4 gelu(x+bias)->fp16 Cp | 5 store x*oscale
template<int EPI, int HALF>
__global__ __launch_bounds__(256) void hgemm(
    const __nv_bfloat16* __restrict__ A, const __nv_bfloat16* __restrict__ Bm,
    float* __restrict__ C, __nv_bfloat16* __restrict__ Cp,
    const float* __restrict__ bias,
    int Mreal, int N, int K, float oscale)
{
    __shared__ __nv_bfloat16 As[2][128*40];
    __shared__ __nv_bfloat16 Bs[2][128*40];
    const int tid = threadIdx.x;
    const int mBase = blockIdx.x*128, cBase = blockIdx.y*128;
    const __nv_bfloat16* pA = A + (size_t)mBase*K;
    const __nv_bfloat16* pB = Bm + (size_t)cBase*K;
    const int warp = tid>>5, lane = tid&31;
    const int wm = warp&3, wn = warp>>2;
    float acc[2][8][4];
    #pragma unroll
    for (int i=0;i<2;i++)
        #pragma unroll
        for (int j=0;j<8;j++)
            #pragma unroll
            for (int q=0;q<4;q++) acc[i][j][q] = 0.f;

    #define PREFETCH(ck, buf) do { \
        int _k0 = (ck)*32; \
        _Pragma("unroll") \
        for (int _t=0; _t<4; _t++){ \
            int _j = _t*256 + tid; \
            int _jj = _j & 511; \
            int _r = _jj>>2, _seg = _jj&3; \
            const __nv_bfloat16* _src = ((_j < 512) ? pA : pB) + (size_t)_r*K + _k0 + _seg*8; \
            uint32_t _dst = smem_u32(((_j < 512) ? &As[buf][0] : &Bs[buf][0]) + _r*40 + _seg*8); \
            CP_ASYNC16(_dst, _src); \
        } \
        CP_COMMIT(); \
    } while(0)

    const int nck = K >> 5;
    PREFETCH(0, 0);
    for (int ck = 0; ck < nck; ck++){
        if (ck + 1 < nck){ PREFETCH(ck+1, (ck+1)&1); CP_WAIT(1); }
        else             { CP_WAIT(0); }
        __syncthreads();
        const __nv_bfloat16* as = &As[ck&1][0];
        const __nv_bfloat16* bs = &Bs[ck&1][0];
        #pragma unroll
        for (int ks=0; ks<2; ks++){
            const int kc = ks*16;
            uint32_t a[2][4], bfr[8][2];
            #pragma unroll
            for (int mt=0; mt<2; mt++){
                int row = wm*32 + mt*16 + (lane&7) + ((lane>>3)&1)*8;
                int col = kc + (lane>>4)*8;
                uint32_t ad = smem_u32(as + row*40 + col);
                LDSM4(a[mt][0], a[mt][1], a[mt][2], a[mt][3], ad);
            }
            #pragma unroll
            for (int p=0; p<4; p++){
                int row = wn*64 + p*16 + (lane>>4)*8 + (lane&7);
                int col = kc + ((lane>>3)&1)*8;
                uint32_t bd = smem_u32(bs + row*40 + col);
                uint32_t r0,r1,r2,r3;
                LDSM4(r0,r1,r2,r3, bd);
                bfr[p*2][0]=r0; bfr[p*2][1]=r1; bfr[p*2+1][0]=r2; bfr[p*2+1][1]=r3;
            }
            #pragma unroll
            for (int mt=0; mt<2; mt++)
                #pragma unroll
                for (int nt=0; nt<8; nt++){
                    if (HALF) { MMA_F16(acc[mt][nt], a[mt], bfr[nt]); }
                    else      { MMA_BF16(acc[mt][nt], a[mt], bfr[nt]); }
                }
        }
        __syncthreads();
    }
    #undef PREFETCH

    const int g = lane>>2, tg = lane&3;
    #pragma unroll
    for (int mt=0; mt<2; mt++){
        int rbase = mBase + wm*32 + mt*16 + g;
        #pragma unroll
        for (int half=0; half<2; half++){
            int r = rbase + half*8;
            if (r >= Mreal) continue;
            #pragma unroll
            for (int nt=0; nt<8; nt++){
                int c0 = cBase + wn*64 + nt*8 + tg*2;
                float v0 = acc[mt][nt][half*2], v1 = acc[mt][nt][half*2+1];
                if (EPI == 4){
                    float g0 = geluf(v0 + bias[c0]), g1 = geluf(v1 + bias[c0+1]);
                    __half* pp = (__half*)Cp + (size_t)r*N + c0;
                    *(__half2*)pp = __floats2half2_rn(g0, g1);
                } else {
                    float* cp = &C[(size_t)r*N + c0];
                    if (EPI == 0){
                        *(float2*)cp = make_float2(v0, v1);
                    } else if (EPI == 5){
                        *(float2*)cp = make_float2(v0*oscale, v1*oscale);
                    } else if (EPI == 2){
                        float2 c = *(float2*)cp;
                        *(float2*)cp = make_float2(c.x + v0 + bias[c0], c.y + v1 + bias[c0+1]);
                    } else {
                        float2 c = *(float2*)cp;
                        *(float2*)cp = make_float2(c.x + v0, c.y + v1);
                    }
                }
            }
        }
    }
}

// ---------------- grouped per-node GEMM (agg=g_ff, res=g_q) ----------------
#define SM_GRP ((128*132 + 96*128)*4)
__global__ __launch_bounds__(256) void k_group()
{
    extern __shared__ float sm[];
    float* s_w = sm;
    float* s_a = sm + 128*132;
    const int n = blockIdx.x, tid = threadIdx.x;
    const float* wb = g_pw + (size_t)n*C_ND*C_ND;
    const float* ab = g_ff + (size_t)n*C_BL*C_ND;
    for (int i = tid; i < (C_ND*C_ND)/4; i += 256){
        int e = i<<2, r = e>>7, c = e&127;
        *(float4*)&s_w[r*132+c] = *(const float4*)(wb+e);
    }
    for (int i = tid; i < (C_BL*C_ND)/4; i += 256)
        ((float4*)s_a)[i] = ((const float4*)ab)[i];
    __syncthreads();
    const int ty = tid>>4, tx = tid&15;
    float acc[6][8];
    #pragma unroll
    for (int i=0;i<6;i++)
        #pragma unroll
        for (int j=0;j<8;j++) acc[i][j]=0.f;
    #pragma unroll 4
    for (int k=0;k<C_ND;k++){
        float4 b0 = *(const float4*)&s_w[k*132 + tx*8];
        float4 b1 = *(const float4*)&s_w[k*132 + tx*8+4];
        float bv[8]={b0.x,b0.y,b0.z,b0.w,b1.x,b1.y,b1.z,b1.w};
        #pragma unroll
        for (int i=0;i<6;i++){
            float a = s_a[(ty*6+i)*C_ND + k];
            #pragma unroll
            for (int j=0;j<8;j++) acc[i][j] = fmaf(a, bv[j], acc[i][j]);
        }
    }
    float* ob = g_q + (size_t)n*C_BL*C_ND;
    #pragma unroll
    for (int i=0;i<6;i++){
        #pragma unroll
        for (int jj=0;jj<2;jj++){
            float4 vv = make_float4(acc[i][jj*4],acc[i][jj*4+1],acc[i][jj*4+2],acc[i][jj*4+3]);
            *(float4*)(ob + (ty*6+i)*C_ND + tx*8 + jj*4) = vv;
        }
    }
}

// ---------------- GroupNorm stats (res = g_q) ----------------
__global__ __launch_bounds__(256) void k_gnred()
{
    int bl = blockIdx.x>>2, g = blockIdx.x&3;
    int base = bl*C_ND + g*32;
    float s = 0.f, ss = 0.f;
    for (int i = threadIdx.x; i < C_NN*32; i += 256){
        int n = i>>5, o = i&31;
        float v = g_q[(size_t)n*C_BL*C_ND + base + o];
        s += v; ss += v*v;
    }
    __shared__ float r1[256], r2[256];
    r1[threadIdx.x]=s; r2[threadIdx.x]=ss; __syncthreads();
    for (int st=128; st>0; st>>=1){
        if (threadIdx.x < st){ r1[threadIdx.x]+=r1[threadIdx.x+st]; r2[threadIdx.x]+=r2[threadIdx.x+st]; }
        __syncthreads();
    }
    if (threadIdx.x == 0){
        float mean = r1[0]/(C_NN*32.0f);
        float var = r2[0]/(C_NN*32.0f) - mean*mean;
        g_gmu[blockIdx.x] = mean;
        g_grs[blockIdx.x] = rsqrtf(var + 1e-5f);
    }
}

// ---------------- final fused (res = g_q) ----------------
__global__ __launch_bounds__(128) void k_final(
    const float* __restrict__ gn_g, const float* __restrict__ gn_b,
    const float* __restrict__ p2_w, const float* __restrict__ p2_b,
    const float* __restrict__ p1_w, const float* __restrict__ p1_b,
    float* __restrict__ out)
{
    int bn = blockIdx.x, b = bn / C_NN, n = bn % C_NN;
    int lane = threadIdx.x & 31, warp = threadIdx.x >> 5;
    __shared__ float s_s[C_NL];
    int d0 = lane*4, g = d0 >> 5;
    float4 gg = *(const float4*)(gn_g + d0);
    float4 gb = *(const float4*)(gn_b + d0);
    float4 pw = *(const float4*)(p2_w + d0);
    float p2b = p2_b[0];
    for (int l = warp; l < C_NL; l += 4){
        int bl = b*C_NL + l;
        float mu = g_gmu[bl*4 + g], rs = g_grs[bl*4 + g];
        float4 x = *(const float4*)(g_q + (size_t)n*C_BL*C_ND + bl*C_ND + d0);
        float dot = ((x.x-mu)*rs*gg.x+gb.x)*pw.x + ((x.y-mu)*rs*gg.y+gb.y)*pw.y
                  + ((x.z-mu)*rs*gg.z+gb.z)*pw.z + ((x.w-mu)*rs*gg.w+gb.w)*pw.w;
        #pragma unroll
        for (int o=16;o;o>>=1) dot += __shfl_xor_sync(~0u, dot, o);
        if (lane == 0){
            float sv = dot + p2b;
            s_s[l] = sv / (1.f + expf(-sv));
        }
    }
    __syncthreads();
    if (threadIdx.x < C_NLOUT){
        float acc = p1_b[threadIdx.x];
        #pragma unroll
        for (int l=0;l<C_NL;l++) acc = fmaf(p1_w[threadIdx.x*C_NL + l], s_s[l], acc);
        out[(size_t)b*C_NLOUT*C_NN + threadIdx.x*C_NN + n] = acc + g_mean[bn];
    }
}

// ---------------- driver ----------------
extern "C" void kernel_launch(void* const* d_in, const int* in_sizes, int n_in,
                              void* d_out, int out_size)
{
    const float* x_enc = (const float*)d_in[0];
    const float* adj   = (const float*)d_in[1];
    const float* pe_raw= (const float*)d_in[2];
    const float* conv_w= (const float*)d_in[3];
    const float* pos_w = (const float*)d_in[4];
    const float* pos_b = (const float*)d_in[5];
    const float* wq    = (const float*)d_in[6];
    const float* wk    = (const float*)d_in[7];
    const float* wv    = (const float*)d_in[8];
    const float* wo    = (const float*)d_in[9];
    const float* ln1_g = (const float*)d_in[10];
    const float* ln1_b = (const float*)d_in[11];
    const float* ff_w1 = (const float*)d_in[12];
    const float* ff_b1 = (const float*)d_in[13];
    const float* ff_w2 = (const float*)d_in[14];
    const float* ff_b2 = (const float*)d_in[15];
    const float* ln2_g = (const float*)d_in[16];
    const float* ln2_b = (const float*)d_in[17];
    const float* wpool = (const float*)d_in[18];
    const float* gn_g  = (const float*)d_in[19];
    const float* gn_b  = (const float*)d_in[20];
    const float* p2_w  = (const float*)d_in[21];
    const float* p2_b  = (const float*)d_in[22];
    const float* p1_w  = (const float*)d_in[23];
    const float* p1_b  = (const float*)d_in[24];
    float* out = (float*)d_out;

    cudaFuncSetAttribute(k_attn,  cudaFuncAttributeMaxDynamicSharedMemorySize, SM_ATTN);
    cudaFuncSetAttribute(k_group, cudaFuncAttributeMaxDynamicSharedMemorySize, SM_GRP);

    float *penc, *pq, *pkk, *pv, *pff, *ppe, *ppe2, *ppw;
    __nv_bfloat16 *pa2, *pb2, *pap, *pbp;
    cudaGetSymbolAddress((void**)&penc,  g_enc);
    cudaGetSymbolAddress((void**)&pq,    g_q);
    cudaGetSymbolAddress((void**)&pkk,   g_kk);
    cudaGetSymbolAddress((void**)&pv,    g_v);
    cudaGetSymbolAddress((void**)&pff,   g_ff);
    cudaGetSymbolAddress((void**)&ppe,   g_pe);
    cudaGetSymbolAddress((void**)&ppe2,  g_pe2);
    cudaGetSymbolAddress((void**)&ppw,   g_pw);
    cudaGetSymbolAddress((void**)&pa2,   g_a2);
    cudaGetSymbolAddress((void**)&pb2,   g_b2);
    cudaGetSymbolAddress((void**)&pap,   g_ap);
    cudaGetSymbolAddress((void**)&pbp,   g_bp);

    __half* pffp16 = (__half*)pb2;   // FF2 fp16 input aliases g_b2
    float* pagg = pff;               // spatial agg aliases g_ff
    __half* pap16 = (__half*)pap;    // fp16 activation view
    __half* pbp16 = (__half*)pbp;    // fp16 weight view

    k_embed<<<C_BN, 128>>>(x_enc, conv_w);
    k_pe<<<(C_NN*C_ND + 255)/256, 256>>>(pe_raw, pos_w, pos_b);
    k_split_adj_h<<<(int)(((size_t)MPAD*KPAD + 255)/256), 256>>>(adj);

    // LN1 -> fp16; q/k/v projections (fp16 plain, K=128)
    k_ln_h<<<C_ROWS/8, 256>>>(penc, ln1_g, ln1_b, pap16);
    dim3 gP(C_ROWS/128, 1);
    k_packW_h<<<(128*128+255)/256, 256>>>(wq, pbp16, 128*128);
    hgemm<0,1><<<gP, 256>>>(pap, pbp, pq, nullptr, nullptr, C_ROWS, 128, 128, 1.f);
    k_packW_h<<<(128*128+255)/256, 256>>>(wk, pbp16, 128*128);
    hgemm<0,1><<<gP, 256>>>(pap, pbp, pkk, nullptr, nullptr, C_ROWS, 128, 128, 1.f);
    k_packW_h<<<(128*128+255)/256, 256>>>(wv, pbp16, 128*128);
    hgemm<0,1><<<gP, 256>>>(pap, pbp, pv, nullptr, nullptr, C_ROWS, 128, 128, 1.f);

    k_softmax_d<<<C_ROWS/8, 256>>>(pq);
    k_softmax_L<<<C_BN, 128>>>(pkk);
    k_attn<<<C_BN, 256, SM_ATTN>>>();       // writes fp16 att0 into g_ap

    // enc += att0 @ wo^T (fp16, K=128)
    k_packW_h<<<(128*128+255)/256, 256>>>(wo, pbp16, 128*128);
    hgemm<3,1><<<gP, 256>>>(pap, pbp, penc, nullptr, nullptr, C_ROWS, 128, 128, 1.f);

    // FF block: LN2 -> fp16; FF1 gelu->fp16 (EPI=4); FF2 accumulate (K=512)
    k_ln_h<<<C_ROWS/8, 256>>>(penc, ln2_g, ln2_b, pap16);
    k_packW_h<<<(512*128+255)/256, 256>>>(ff_w1, pbp16, 512*128);
    hgemm<4,1><<<dim3(C_ROWS/128, 4), 256>>>(pap, pbp, nullptr, pb2, ff_b1, C_ROWS, 512, 128, 1.f);
    k_packW_h<<<(128*512+255)/256, 256>>>(ff_w2, pbp16, 128*512);
    hgemm<2,1><<<gP, 256>>>(pb2, pbp, penc, nullptr, ff_b2, C_ROWS, 128, 512, 1.f);

    // spatial: agg = adj @ nf  — plain fp16, A scaled x1024, epilogue x(1/1024)
    k_bt_h<<<dim3(KPAD/32, C_ND/32, C_BL), 256>>>(pb2);
    hgemm<5,1><<<dim3(MPAD/128, NCOL/128), 256>>>(pa2, pb2, pagg, nullptr, nullptr,
                                                  C_NN, NCOL, KPAD, 1.f/1024.f);

    // pe2 = adj @ pe (fp32); pw = pe2 @ wpool (bf16 split-K3, protected path)
    sgemm_nn<<<dim3(24, 1), 256>>>(adj, ppe, ppe2, C_NN, 128, C_NN);
    k_packA<<<(int)(((size_t)MPAD*128 + 255)/256), 256>>>(ppe2, pap, C_NN, 128, MPAD);
    k_packBt<<<(16384*128+255)/256, 256>>>(wpool, pbp, 16384, 128);
    hgemm<0,0><<<dim3(MPAD/128, 128), 256>>>(pap, pbp, ppw, nullptr, nullptr, C_NN, 16384, 384, 1.f);

    k_group<<<C_NN, 256, SM_GRP>>>();
    k_gnred<<<C_BL*4, 256>>>();
    k_final<<<C_BN, 128>>>(gn_g, gn_b, p2_w, p2_b, p1_w, p1_b, out);
}